// round 5
// baseline (speedup 1.0000x reference)
#include <cuda_runtime.h>
#include <cuda_bf16.h>
#include <cstdint>

#define N_NODES 50000
#define N_EDGES 600000
#define D 128
#define K2 256             // concat [agg|h] K dimension
#define NCHUNK 49          // ceil(50000/1024)

// ================= helpers ===================================================
__device__ __forceinline__ uint32_t smem_u32(const void* p) {
    uint32_t a;
    asm("{ .reg .u64 t; cvta.to.shared.u64 t, %1; cvt.u32.u64 %0, t; }" : "=r"(a) : "l"(p));
    return a;
}
#define SWZ128(off) ((off) ^ (((off) >> 3) & 0x70))

__device__ __forceinline__ void ldsm_x4(uint32_t* r, uint32_t addr) {
    asm volatile("ldmatrix.sync.aligned.m8n8.x4.shared.b16 {%0,%1,%2,%3}, [%4];"
        : "=r"(r[0]), "=r"(r[1]), "=r"(r[2]), "=r"(r[3]) : "r"(addr));
}
__device__ __forceinline__ void mma_bf16(float* d, const uint32_t* a, const uint32_t* b) {
    asm volatile(
        "mma.sync.aligned.m16n8k16.row.col.f32.bf16.bf16.f32 "
        "{%0,%1,%2,%3}, {%4,%5,%6,%7}, {%8,%9}, {%0,%1,%2,%3};"
        : "+f"(d[0]), "+f"(d[1]), "+f"(d[2]), "+f"(d[3])
        : "r"(a[0]), "r"(a[1]), "r"(a[2]), "r"(a[3]), "r"(b[0]), "r"(b[1]));
}
__device__ __forceinline__ void cp_async16(uint32_t dst, const void* src) {
    asm volatile("cp.async.cg.shared.global [%0], [%1], 16;" :: "r"(dst), "l"(src));
}
#define CP_COMMIT() asm volatile("cp.async.commit_group;" ::: "memory")
#define CP_WAIT0()  asm volatile("cp.async.wait_group 0;" ::: "memory")
#define BAR1_256()  asm volatile("bar.sync 1, 256;" ::: "memory")

__device__ __forceinline__ uint32_t pack2bf(float a, float b) {
    __nv_bfloat162 t = __floats2bfloat162_rn(a, b);
    return *(uint32_t*)&t;
}

// ================ scratch (static device globals) ============================
__device__ int   g_is64;
__device__ int   g_cnt[N_NODES];
__device__ int   g_rowptr[N_NODES + 1];
__device__ int   g_cursor[N_NODES];
__device__ int   g_bsum[64];
__device__ int   g_srcidx[N_EDGES];
__device__ float g_h1[(size_t)N_NODES * D];
__device__ float g_h2[(size_t)N_NODES * D];
__device__ __nv_bfloat16 g_Ahi[(size_t)N_NODES * K2];   // only cols [128..256) used
__device__ __nv_bfloat16 g_Alo[(size_t)N_NODES * K2];
__device__ __nv_bfloat16 g_Bhi[3 * 128 * K2];
__device__ __nv_bfloat16 g_Blo[3 * 128 * K2];

__device__ __forceinline__ int edge_val(const void* ei, int idx) {
    if (g_is64) return (int)((const long long*)ei)[idx];
    return ((const int*)ei)[idx];
}

// ================ dtype detection + CSR build ================================
__global__ void zero_detect_kernel(const int* __restrict__ ei32) {
    int i = blockIdx.x * blockDim.x + threadIdx.x;
    if (i < N_NODES) g_cnt[i] = 0;
    if (i == 0) {
        int is64 = 1;
        for (int q = 0; q < 64; q++)
            if (ei32[2 * q + 1] != 0) { is64 = 0; break; }
        g_is64 = is64;
    }
}
__global__ void count_kernel(const void* __restrict__ ei) {
    int e = blockIdx.x * blockDim.x + threadIdx.x;
    if (e < N_EDGES) atomicAdd(&g_cnt[edge_val(ei, N_EDGES + e)], 1);
}
__global__ void scan_partial_kernel() {
    __shared__ int s[1024];
    int i = blockIdx.x * 1024 + threadIdx.x;
    int v = (i < N_NODES) ? g_cnt[i] : 0;
    s[threadIdx.x] = v;
    __syncthreads();
    for (int off = 512; off > 0; off >>= 1) {
        if (threadIdx.x < off) s[threadIdx.x] += s[threadIdx.x + off];
        __syncthreads();
    }
    if (threadIdx.x == 0) g_bsum[blockIdx.x] = s[0];
}
__global__ void scan_bsums_kernel() {
    if (threadIdx.x == 0) {
        int acc = 0;
        for (int i = 0; i < NCHUNK; i++) { int v = g_bsum[i]; g_bsum[i] = acc; acc += v; }
    }
}
__global__ void scan_write_kernel() {
    __shared__ int s[1024];
    int i = blockIdx.x * 1024 + threadIdx.x;
    int v = (i < N_NODES) ? g_cnt[i] : 0;
    s[threadIdx.x] = v;
    __syncthreads();
    for (int off = 1; off < 1024; off <<= 1) {
        int t = (threadIdx.x >= off) ? s[threadIdx.x - off] : 0;
        __syncthreads();
        s[threadIdx.x] += t;
        __syncthreads();
    }
    if (i < N_NODES) {
        int excl = s[threadIdx.x] - v + g_bsum[blockIdx.x];
        g_rowptr[i] = excl;
        g_cursor[i] = excl;
        if (i == N_NODES - 1) g_rowptr[N_NODES] = excl + v;
    }
}
__global__ void fill_kernel(const void* __restrict__ ei) {
    int e = blockIdx.x * blockDim.x + threadIdx.x;
    if (e < N_EDGES) {
        int d = edge_val(ei, N_EDGES + e);
        int s = edge_val(ei, e);
        g_srcidx[atomicAdd(&g_cursor[d], 1)] = s;
    }
}

// ============== weight prep: Bcat[n,k] split to bf16 hi/lo ===================
__global__ void prep_weights_kernel(const float* __restrict__ Wl1, const float* __restrict__ Wr1,
                                    const float* __restrict__ Wl2, const float* __restrict__ Wr2,
                                    const float* __restrict__ Wl3, const float* __restrict__ Wr3) {
    int i = blockIdx.x * blockDim.x + threadIdx.x;   // 3*128*256
    if (i >= 3 * 128 * K2) return;
    int l = i / (128 * K2);
    int n = (i / K2) % 128;
    int k = i % K2;
    const float* Wl = (l == 0) ? Wl1 : (l == 1) ? Wl2 : Wl3;
    const float* Wr = (l == 0) ? Wr1 : (l == 1) ? Wr2 : Wr3;
    float v = (k < D) ? Wl[n * D + k] : Wr[n * D + (k - D)];
    __nv_bfloat16 hi = __float2bfloat16(v);
    float lo = v - __bfloat162float(hi);
    g_Bhi[i] = hi;
    g_Blo[i] = __float2bfloat16(lo);
}

// ============== x -> bf16 hi/lo into A cols [128..256) =======================
__global__ void xconv_kernel(const float* __restrict__ x) {
    int i = blockIdx.x * blockDim.x + threadIdx.x;   // one float4 each
    if (i >= N_NODES * 32) return;
    int row = i >> 5, c4 = i & 31;
    float4 v = *(const float4*)(x + (size_t)row * D + c4 * 4);
    __nv_bfloat16 h0 = __float2bfloat16(v.x), h1 = __float2bfloat16(v.y);
    __nv_bfloat16 h2 = __float2bfloat16(v.z), h3 = __float2bfloat16(v.w);
    uint2 hp, lp;
    hp.x = pack2bf(v.x, v.y); hp.y = pack2bf(v.z, v.w);
    lp.x = pack2bf(v.x - __bfloat162float(h0), v.y - __bfloat162float(h1));
    lp.y = pack2bf(v.z - __bfloat162float(h2), v.w - __bfloat162float(h3));
    size_t off = (size_t)row * K2 + D + c4 * 4;
    *(uint2*)(g_Ahi + off) = hp;
    *(uint2*)(g_Alo + off) = lp;
}

// ================= fused layer: agg + bf16 mma.sync GEMM =====================
// out[M,128] = relu([mean_agg(hsrc) | self] @ Bcat^T + bias), 3-term bf16 split.
// 384 threads: warps 0-7 MMA (128x128 CTA tile, 2x4 warp grid, 64x32 warp tile),
// warps 8-11 gather this CTA's 128 rows -> resident bf16 hi/lo agg tiles.
// Chunk schedule: 6 self-feature chunks (cols 128..256, streamed) first --
// overlapping the gather -- then __syncthreads join, then 6 agg chunks.
#define TILE_B  16384                  // 128 rows x 128 bytes (64 bf16)
#define SMF_BIAS 0
#define SMF_AGG  1024                  // aggHi0, aggHi1, aggLo0, aggLo1
#define SMF_AST  (SMF_AGG + 4 * TILE_B)
#define SMF_BST  (SMF_AST + 2 * TILE_B)
#define SMF_TOTAL (SMF_BST + 2 * TILE_B)   // 132096 bytes -> 1 CTA/SM

__constant__ int c_aRes[12]   = {-1,-1,-1,-1,-1,-1, 0, 1, 0, 1, 2, 3};
__constant__ int c_aHiSel[12] = { 1, 1, 1, 1, 0, 0, 0, 0, 0, 0, 0, 0};
__constant__ int c_aK[12]     = {128,192,128,192,128,192, 0, 0, 0, 0, 0, 0};
__constant__ int c_bHiSel[12] = { 1, 1, 0, 0, 1, 1, 1, 1, 0, 0, 1, 1};
__constant__ int c_bK[12]     = {128,192,128,192,128,192, 0,64, 0,64, 0,64};

__global__ __launch_bounds__(384)
void fused_layer(const float* __restrict__ hsrc,
                 const __nv_bfloat16* __restrict__ Ahi, const __nv_bfloat16* __restrict__ Alo,
                 const __nv_bfloat16* __restrict__ Bhi, const __nv_bfloat16* __restrict__ Blo,
                 const float* __restrict__ bias, float* __restrict__ out,
                 __nv_bfloat16* __restrict__ nAhi, __nv_bfloat16* __restrict__ nAlo,
                 int write_next) {
    extern __shared__ char smem[];
    const uint32_t sb = smem_u32(smem);
    const int tid = threadIdx.x;
    const int wid = tid >> 5, lane = tid & 31;
    const int m0 = blockIdx.x * 128;

    // ---------------- gather warps (8..11) ----------------------------------
    if (wid >= 8) {
        int gw = wid - 8;
        for (int i = 0; i < 32; i++) {
            int lr = gw * 32 + i;
            int gm = m0 + lr;
            if (gm >= N_NODES) gm = N_NODES - 1;
            int beg = g_rowptr[gm], end = g_rowptr[gm + 1];
            float4 s0 = make_float4(0.f,0.f,0.f,0.f), s1 = s0, s2 = s0, s3 = s0;
            int e = beg;
            for (; e + 4 <= end; e += 4) {
                int j0 = g_srcidx[e],     j1 = g_srcidx[e + 1];
                int j2 = g_srcidx[e + 2], j3 = g_srcidx[e + 3];
                float4 v0 = *(const float4*)(hsrc + (size_t)j0 * D + lane * 4);
                float4 v1 = *(const float4*)(hsrc + (size_t)j1 * D + lane * 4);
                float4 v2 = *(const float4*)(hsrc + (size_t)j2 * D + lane * 4);
                float4 v3 = *(const float4*)(hsrc + (size_t)j3 * D + lane * 4);
                s0.x += v0.x; s0.y += v0.y; s0.z += v0.z; s0.w += v0.w;
                s1.x += v1.x; s1.y += v1.y; s1.z += v1.z; s1.w += v1.w;
                s2.x += v2.x; s2.y += v2.y; s2.z += v2.z; s2.w += v2.w;
                s3.x += v3.x; s3.y += v3.y; s3.z += v3.z; s3.w += v3.w;
            }
            for (; e < end; e++) {
                int j = g_srcidx[e];
                float4 v = *(const float4*)(hsrc + (size_t)j * D + lane * 4);
                s0.x += v.x; s0.y += v.y; s0.z += v.z; s0.w += v.w;
            }
            float inv = 1.0f / fmaxf((float)(end - beg), 1.0f);
            float4 m;
            m.x = ((s0.x + s1.x) + (s2.x + s3.x)) * inv;
            m.y = ((s0.y + s1.y) + (s2.y + s3.y)) * inv;
            m.z = ((s0.z + s1.z) + (s2.z + s3.z)) * inv;
            m.w = ((s0.w + s1.w) + (s2.w + s3.w)) * inv;
            __nv_bfloat16 h0 = __float2bfloat16(m.x), h1 = __float2bfloat16(m.y);
            __nv_bfloat16 h2 = __float2bfloat16(m.z), h3 = __float2bfloat16(m.w);
            uint2 hp, lp;
            hp.x = pack2bf(m.x, m.y); hp.y = pack2bf(m.z, m.w);
            lp.x = pack2bf(m.x - __bfloat162float(h0), m.y - __bfloat162float(h1));
            lp.y = pack2bf(m.z - __bfloat162float(h2), m.w - __bfloat162float(h3));
            int chunk = lane >> 4;                         // cols 0..63 vs 64..127
            uint32_t off = SWZ128((uint32_t)(lr * 128 + (lane & 15) * 8));
            *(uint2*)(smem + SMF_AGG + chunk * TILE_B + off) = hp;
            *(uint2*)(smem + SMF_AGG + 2 * TILE_B + chunk * TILE_B + off) = lp;
        }
        __syncthreads();    // join: agg tiles ready for MMA warps
        return;
    }

    // ---------------- MMA warps (0..7), 256 threads --------------------------
    const int wm = wid >> 2, wn = wid & 3;
    if (tid < 128) *(float*)(smem + SMF_BIAS + tid * 4) = bias[tid];

    float acc[4][4][4];
#pragma unroll
    for (int i = 0; i < 4; i++)
#pragma unroll
        for (int j = 0; j < 4; j++)
#pragma unroll
            for (int q = 0; q < 4; q++) acc[i][j][q] = 0.f;

    auto prefetch = [&](int s, int buf) {
        const __nv_bfloat16* Bp = c_bHiSel[s] ? Bhi : Blo;
        uint32_t sB = sb + SMF_BST + buf * TILE_B;
        int bk = c_bK[s];
#pragma unroll
        for (int t = 0; t < 4; t++) {
            int u = tid + t * 256;               // 0..1023
            int row = u >> 3, f4 = u & 7;
            cp_async16(sB + SWZ128((uint32_t)(row * 128 + f4 * 16)),
                       Bp + (size_t)row * K2 + bk + f4 * 8);
        }
        if (c_aRes[s] < 0) {
            const __nv_bfloat16* Ap = c_aHiSel[s] ? Ahi : Alo;
            uint32_t sA = sb + SMF_AST + buf * TILE_B;
            int ak = c_aK[s];
#pragma unroll
            for (int t = 0; t < 4; t++) {
                int u = tid + t * 256;
                int row = u >> 3, f4 = u & 7;
                int gm = m0 + row;
                if (gm >= N_NODES) gm = N_NODES - 1;
                cp_async16(sA + SWZ128((uint32_t)(row * 128 + f4 * 16)),
                           Ap + (size_t)gm * K2 + ak + f4 * 8);
            }
        }
    };

    prefetch(0, 0);
    CP_COMMIT();

    for (int s = 0; s < 12; s++) {
        CP_WAIT0();
        BAR1_256();                       // buffers ready + prev consumers done
        if (s + 1 < 12) { prefetch(s + 1, (s + 1) & 1); CP_COMMIT(); }
        if (s == 6) __syncthreads();      // wait for gather warps (agg tiles)

        uint32_t sA = (c_aRes[s] >= 0) ? sb + SMF_AGG + c_aRes[s] * TILE_B
                                       : sb + SMF_AST + (s & 1) * TILE_B;
        uint32_t sB = sb + SMF_BST + (s & 1) * TILE_B;
#pragma unroll
        for (int kk = 0; kk < 4; kk++) {
            uint32_t a[4][4], b[4][2];
#pragma unroll
            for (int mf = 0; mf < 4; mf++) {
                int row  = wm * 64 + mf * 16 + (lane & 15);
                int colb = kk * 32 + (lane >> 4) * 16;
                ldsm_x4(a[mf], sA + SWZ128((uint32_t)(row * 128 + colb)));
            }
#pragma unroll
            for (int nh = 0; nh < 2; nh++) {
                uint32_t r[4];
                int row  = wn * 32 + nh * 16 + (lane & 7) + ((lane >> 4) << 3);
                int colb = kk * 32 + ((lane >> 3) & 1) * 16;
                ldsm_x4(r, sB + SWZ128((uint32_t)(row * 128 + colb)));
                b[nh * 2][0] = r[0]; b[nh * 2][1] = r[1];
                b[nh * 2 + 1][0] = r[2]; b[nh * 2 + 1][1] = r[3];
            }
#pragma unroll
            for (int mf = 0; mf < 4; mf++)
#pragma unroll
                for (int nf = 0; nf < 4; nf++)
                    mma_bf16(acc[mf][nf], a[mf], b[nf]);
        }
    }

    // epilogue: bias + relu + store fp32 (+ optional next-layer bf16 hi/lo)
    const int qr = lane >> 2;          // 0..7
    const int qc = (lane & 3) * 2;     // 0,2,4,6
#pragma unroll
    for (int mf = 0; mf < 4; mf++) {
        int r0 = m0 + wm * 64 + mf * 16 + qr;
        int r1 = r0 + 8;
#pragma unroll
        for (int nf = 0; nf < 4; nf++) {
            int col = wn * 32 + nf * 8 + qc;
            float b0 = *(const float*)(smem + SMF_BIAS + col * 4);
            float b1 = *(const float*)(smem + SMF_BIAS + (col + 1) * 4);
            float v00 = fmaxf(acc[mf][nf][0] + b0, 0.f);
            float v01 = fmaxf(acc[mf][nf][1] + b1, 0.f);
            float v10 = fmaxf(acc[mf][nf][2] + b0, 0.f);
            float v11 = fmaxf(acc[mf][nf][3] + b1, 0.f);
            if (r0 < N_NODES) {
                *(float2*)(out + (size_t)r0 * D + col) = make_float2(v00, v01);
                if (write_next) {
                    __nv_bfloat16 h0 = __float2bfloat16(v00), h1 = __float2bfloat16(v01);
                    size_t off = (size_t)r0 * K2 + D + col;
                    *(uint32_t*)(nAhi + off) = pack2bf(v00, v01);
                    *(uint32_t*)(nAlo + off) = pack2bf(v00 - __bfloat162float(h0),
                                                       v01 - __bfloat162float(h1));
                }
            }
            if (r1 < N_NODES) {
                *(float2*)(out + (size_t)r1 * D + col) = make_float2(v10, v11);
                if (write_next) {
                    __nv_bfloat16 h0 = __float2bfloat16(v10), h1 = __float2bfloat16(v11);
                    size_t off = (size_t)r1 * K2 + D + col;
                    *(uint32_t*)(nAhi + off) = pack2bf(v10, v11);
                    *(uint32_t*)(nAlo + off) = pack2bf(v10 - __bfloat162float(h0),
                                                       v11 - __bfloat162float(h1));
                }
            }
        }
    }
}

// ================= launch ====================================================
extern "C" void kernel_launch(void* const* d_in, const int* in_sizes, int n_in,
                              void* d_out, int out_size) {
    const float* x  = (const float*)d_in[0];
    const void*  ei = d_in[1];
    const float* Wl1 = (const float*)d_in[2];
    const float* bl1 = (const float*)d_in[3];
    const float* Wr1 = (const float*)d_in[4];
    const float* Wl2 = (const float*)d_in[5];
    const float* bl2 = (const float*)d_in[6];
    const float* Wr2 = (const float*)d_in[7];
    const float* Wl3 = (const float*)d_in[8];
    const float* bl3 = (const float*)d_in[9];
    const float* Wr3 = (const float*)d_in[10];
    float* out = (float*)d_out;

    float *h1, *h2;
    __nv_bfloat16 *Ahi, *Alo, *Bhi, *Blo;
    cudaGetSymbolAddress((void**)&h1,  g_h1);
    cudaGetSymbolAddress((void**)&h2,  g_h2);
    cudaGetSymbolAddress((void**)&Ahi, g_Ahi);
    cudaGetSymbolAddress((void**)&Alo, g_Alo);
    cudaGetSymbolAddress((void**)&Bhi, g_Bhi);
    cudaGetSymbolAddress((void**)&Blo, g_Blo);

    cudaFuncSetAttribute(fused_layer, cudaFuncAttributeMaxDynamicSharedMemorySize, SMF_TOTAL);

    // CSR build + weight/x prep
    zero_detect_kernel<<<(N_NODES + 255) / 256, 256>>>((const int*)ei);
    count_kernel<<<(N_EDGES + 255) / 256, 256>>>(ei);
    scan_partial_kernel<<<NCHUNK, 1024>>>();
    scan_bsums_kernel<<<1, 32>>>();
    scan_write_kernel<<<NCHUNK, 1024>>>();
    fill_kernel<<<(N_EDGES + 255) / 256, 256>>>(ei);
    prep_weights_kernel<<<(3 * 128 * K2 + 255) / 256, 256>>>(Wl1, Wr1, Wl2, Wr2, Wl3, Wr3);
    xconv_kernel<<<(N_NODES * 32 + 255) / 256, 256>>>(x);

    const int GRID = (N_NODES + 127) / 128;   // 391

    // layer 1: agg(x) fused; self = x (cols 128..256 from xconv)
    fused_layer<<<GRID, 384, SMF_TOTAL>>>(x, Ahi, Alo, Bhi, Blo, bl1, h1, Ahi, Alo, 1);
    // layer 2
    fused_layer<<<GRID, 384, SMF_TOTAL>>>(h1, Ahi, Alo, Bhi + 128 * K2, Blo + 128 * K2,
                                          bl2, h2, Ahi, Alo, 1);
    // layer 3 -> final output
    fused_layer<<<GRID, 384, SMF_TOTAL>>>(h2, Ahi, Alo, Bhi + 2 * 128 * K2, Blo + 2 * 128 * K2,
                                          bl3, out, (__nv_bfloat16*)nullptr,
                                          (__nv_bfloat16*)nullptr, 0);
}

// round 9
// speedup vs baseline: 3.5216x; 3.5216x over previous
#include <cuda_runtime.h>
#include <cuda_bf16.h>
#include <cstdint>

#define N_NODES 50000
#define N_EDGES 600000
#define D 128
#define K2 256             // concat [agg|h] K dimension
#define NCHUNK 49          // ceil(50000/1024)

// ================= helpers ===================================================
__device__ __forceinline__ uint32_t smem_u32(const void* p) {
    uint32_t a;
    asm("{ .reg .u64 t; cvta.to.shared.u64 t, %1; cvt.u32.u64 %0, t; }" : "=r"(a) : "l"(p));
    return a;
}
#define SWZ128(off) ((off) ^ (((off) >> 3) & 0x70))

__device__ __forceinline__ void ldsm_x4(uint32_t* r, uint32_t addr) {
    asm volatile("ldmatrix.sync.aligned.m8n8.x4.shared.b16 {%0,%1,%2,%3}, [%4];"
        : "=r"(r[0]), "=r"(r[1]), "=r"(r[2]), "=r"(r[3]) : "r"(addr));
}
__device__ __forceinline__ void mma_bf16(float* d, const uint32_t* a, const uint32_t* b) {
    asm volatile(
        "mma.sync.aligned.m16n8k16.row.col.f32.bf16.bf16.f32 "
        "{%0,%1,%2,%3}, {%4,%5,%6,%7}, {%8,%9}, {%0,%1,%2,%3};"
        : "+f"(d[0]), "+f"(d[1]), "+f"(d[2]), "+f"(d[3])
        : "r"(a[0]), "r"(a[1]), "r"(a[2]), "r"(a[3]), "r"(b[0]), "r"(b[1]));
}
__device__ __forceinline__ void cp_async16(uint32_t dst, const void* src) {
    asm volatile("cp.async.cg.shared.global [%0], [%1], 16;" :: "r"(dst), "l"(src));
}
#define CP_COMMIT() asm volatile("cp.async.commit_group;" ::: "memory")
#define CP_WAIT0()  asm volatile("cp.async.wait_group 0;" ::: "memory")

__device__ __forceinline__ uint32_t pack2bf(float a, float b) {
    __nv_bfloat162 t = __floats2bfloat162_rn(a, b);
    return *(uint32_t*)&t;
}

// ================ scratch (static device globals) ============================
__device__ int   g_is64;
__device__ int   g_cnt[N_NODES];
__device__ int   g_rowptr[N_NODES + 1];
__device__ int   g_cursor[N_NODES];
__device__ int   g_bsum[64];
__device__ int   g_srcidx[N_EDGES];
__device__ float g_h1[(size_t)N_NODES * D];
__device__ float g_h2[(size_t)N_NODES * D];
__device__ __nv_bfloat16 g_Ahi[(size_t)N_NODES * K2];   // cols [0,128)=agg, [128,256)=self
__device__ __nv_bfloat16 g_Alo[(size_t)N_NODES * K2];
__device__ __nv_bfloat16 g_Bhi[3 * 128 * K2];
__device__ __nv_bfloat16 g_Blo[3 * 128 * K2];

__device__ __forceinline__ int edge_val(const void* ei, int idx) {
    if (g_is64) return (int)((const long long*)ei)[idx];
    return ((const int*)ei)[idx];
}

// ================ prologue K1: xconv + weight prep + zero + detect ===========
// blocks [0, 6250): x -> bf16 hi/lo into A cols [128..256)
// blocks [6250, 6634): weight split to Bhi/Blo (3*128*256 = 98304 elems)
// blocks [6634, 6830): zero g_cnt (+ dtype detect in first block)
#define K1_XB 6250
#define K1_WB 384
#define K1_ZB 196
__global__ __launch_bounds__(256)
void prep_all_kernel(const float* __restrict__ x, const int* __restrict__ ei32,
                     const float* __restrict__ Wl1, const float* __restrict__ Wr1,
                     const float* __restrict__ Wl2, const float* __restrict__ Wr2,
                     const float* __restrict__ Wl3, const float* __restrict__ Wr3) {
    int b = blockIdx.x;
    if (b < K1_XB) {
        int i = b * 256 + threadIdx.x;
        if (i >= N_NODES * 32) return;
        int row = i >> 5, c4 = i & 31;
        float4 v = *(const float4*)(x + (size_t)row * D + c4 * 4);
        __nv_bfloat16 h0 = __float2bfloat16(v.x), h1 = __float2bfloat16(v.y);
        __nv_bfloat16 h2 = __float2bfloat16(v.z), h3 = __float2bfloat16(v.w);
        uint2 hp, lp;
        hp.x = pack2bf(v.x, v.y); hp.y = pack2bf(v.z, v.w);
        lp.x = pack2bf(v.x - __bfloat162float(h0), v.y - __bfloat162float(h1));
        lp.y = pack2bf(v.z - __bfloat162float(h2), v.w - __bfloat162float(h3));
        size_t off = (size_t)row * K2 + D + c4 * 4;
        *(uint2*)(g_Ahi + off) = hp;
        *(uint2*)(g_Alo + off) = lp;
    } else if (b < K1_XB + K1_WB) {
        int i = (b - K1_XB) * 256 + threadIdx.x;   // < 98304
        int l = i / (128 * K2);
        int n = (i / K2) % 128;
        int k = i % K2;
        const float* Wl = (l == 0) ? Wl1 : (l == 1) ? Wl2 : Wl3;
        const float* Wr = (l == 0) ? Wr1 : (l == 1) ? Wr2 : Wr3;
        float v = (k < D) ? Wl[n * D + k] : Wr[n * D + (k - D)];
        __nv_bfloat16 hi = __float2bfloat16(v);
        g_Bhi[i] = hi;
        g_Blo[i] = __float2bfloat16(v - __bfloat162float(hi));
    } else {
        int i = (b - K1_XB - K1_WB) * 256 + threadIdx.x;
        if (i < N_NODES) g_cnt[i] = 0;
        if (i == 0) {
            int is64 = 1;
            for (int q = 0; q < 64; q++)
                if (ei32[2 * q + 1] != 0) { is64 = 0; break; }
            g_is64 = is64;
        }
    }
}

// ================ CSR build ==================================================
__global__ void count_kernel(const void* __restrict__ ei) {
    int e = blockIdx.x * blockDim.x + threadIdx.x;
    if (e < N_EDGES) atomicAdd(&g_cnt[edge_val(ei, N_EDGES + e)], 1);
}
__global__ void scan_partial_kernel() {
    __shared__ int s[1024];
    int i = blockIdx.x * 1024 + threadIdx.x;
    int v = (i < N_NODES) ? g_cnt[i] : 0;
    s[threadIdx.x] = v;
    __syncthreads();
    for (int off = 512; off > 0; off >>= 1) {
        if (threadIdx.x < off) s[threadIdx.x] += s[threadIdx.x + off];
        __syncthreads();
    }
    if (threadIdx.x == 0) g_bsum[blockIdx.x] = s[0];
}
__global__ void scan_write_kernel() {
    __shared__ int s[1024];
    __shared__ int s_pre;
    int i = blockIdx.x * 1024 + threadIdx.x;
    int v = (i < N_NODES) ? g_cnt[i] : 0;
    s[threadIdx.x] = v;
    if (threadIdx.x == 0) {             // inline prefix over block sums (<=49)
        int pre = 0;
        for (int t = 0; t < blockIdx.x; t++) pre += g_bsum[t];
        s_pre = pre;
    }
    __syncthreads();
    for (int off = 1; off < 1024; off <<= 1) {
        int t = (threadIdx.x >= off) ? s[threadIdx.x - off] : 0;
        __syncthreads();
        s[threadIdx.x] += t;
        __syncthreads();
    }
    if (i < N_NODES) {
        int excl = s[threadIdx.x] - v + s_pre;
        g_rowptr[i] = excl;
        g_cursor[i] = excl;
        if (i == N_NODES - 1) g_rowptr[N_NODES] = excl + v;
    }
}
__global__ void fill_kernel(const void* __restrict__ ei) {
    int e = blockIdx.x * blockDim.x + threadIdx.x;
    if (e < N_EDGES) {
        int d = edge_val(ei, N_EDGES + e);
        int s = edge_val(ei, e);
        g_srcidx[atomicAdd(&g_cursor[d], 1)] = s;
    }
}

// ===== mean aggregation (warp/node) -> bf16 hi/lo into A cols [0..128) =======
__global__ __launch_bounds__(256)
void agg_kernel(const float* __restrict__ h) {
    int warp = (blockIdx.x * blockDim.x + threadIdx.x) >> 5;
    int lane = threadIdx.x & 31;
    if (warp >= N_NODES) return;
    int beg = g_rowptr[warp];
    int end = g_rowptr[warp + 1];
    float4 s0 = make_float4(0.f,0.f,0.f,0.f), s1 = s0, s2 = s0, s3 = s0;
    int e = beg;
    for (; e + 4 <= end; e += 4) {
        int j0 = g_srcidx[e],     j1 = g_srcidx[e + 1];
        int j2 = g_srcidx[e + 2], j3 = g_srcidx[e + 3];
        float4 v0 = *(const float4*)(h + (size_t)j0 * D + lane * 4);
        float4 v1 = *(const float4*)(h + (size_t)j1 * D + lane * 4);
        float4 v2 = *(const float4*)(h + (size_t)j2 * D + lane * 4);
        float4 v3 = *(const float4*)(h + (size_t)j3 * D + lane * 4);
        s0.x += v0.x; s0.y += v0.y; s0.z += v0.z; s0.w += v0.w;
        s1.x += v1.x; s1.y += v1.y; s1.z += v1.z; s1.w += v1.w;
        s2.x += v2.x; s2.y += v2.y; s2.z += v2.z; s2.w += v2.w;
        s3.x += v3.x; s3.y += v3.y; s3.z += v3.z; s3.w += v3.w;
    }
    for (; e < end; e++) {
        int j = g_srcidx[e];
        float4 v = *(const float4*)(h + (size_t)j * D + lane * 4);
        s0.x += v.x; s0.y += v.y; s0.z += v.z; s0.w += v.w;
    }
    float inv = 1.0f / fmaxf((float)(end - beg), 1.0f);
    float4 m;
    m.x = ((s0.x + s1.x) + (s2.x + s3.x)) * inv;
    m.y = ((s0.y + s1.y) + (s2.y + s3.y)) * inv;
    m.z = ((s0.z + s1.z) + (s2.z + s3.z)) * inv;
    m.w = ((s0.w + s1.w) + (s2.w + s3.w)) * inv;
    __nv_bfloat16 h0 = __float2bfloat16(m.x), h1 = __float2bfloat16(m.y);
    __nv_bfloat16 h2 = __float2bfloat16(m.z), h3 = __float2bfloat16(m.w);
    uint2 hp, lp;
    hp.x = pack2bf(m.x, m.y); hp.y = pack2bf(m.z, m.w);
    lp.x = pack2bf(m.x - __bfloat162float(h0), m.y - __bfloat162float(h1));
    lp.y = pack2bf(m.z - __bfloat162float(h2), m.w - __bfloat162float(h3));
    size_t off = (size_t)warp * K2 + lane * 4;
    *(uint2*)(g_Ahi + off) = hp;
    *(uint2*)(g_Alo + off) = lp;
}

// ================= bf16 mma.sync GEMM (A-tile dedup schedule) ================
// out = relu([agg|self] @ [Wl|Wr]^T + b), 3-term bf16 split over 12 chunks.
// Schedule reuses each A-tile for 2 B-chunks where possible: 8 A-loads, 12 B.
//   s:      0        1        2        3        4        5
//      Ahi128*Bhi Ahi128*Blo Ahi192*Bhi Ahi192*Blo Alo128*Bhi Alo192*Bhi
//   s:      6        7        8        9       10       11
//      Ahi0*Bhi   Ahi0*Blo   Ahi64*Bhi  Ahi64*Blo  Alo0*Bhi   Alo64*Bhi
#define TILE_B  16384
#define SM_BIAS 0
#define SM_A0   1024
#define SM_B0   (1024 + 2 * TILE_B)
#define SM_TOTAL (1024 + 4 * TILE_B)   // 66560 -> 3 CTAs/SM

__constant__ int c_aNew[12] = {1,0,1,0,1,1, 1,0,1,0,1,1};
__constant__ int c_aBuf[12] = {0,0,1,1,0,1, 0,0,1,1,0,1};
__constant__ int c_aHi[12]  = {1,1,1,1,0,0, 1,1,1,1,0,0};
__constant__ int c_bHi[12]  = {1,0,1,0,1,1, 1,0,1,0,1,1};
__constant__ int c_K[12]    = {128,128,192,192,128,192, 0,0,64,64,0,64};

__global__ __launch_bounds__(256)
void gemm_tc(const __nv_bfloat16* __restrict__ Bhi, const __nv_bfloat16* __restrict__ Blo,
             const float* __restrict__ bias, float* __restrict__ out,
             __nv_bfloat16* __restrict__ nAhi, __nv_bfloat16* __restrict__ nAlo,
             int write_next) {
    extern __shared__ char smem[];
    const uint32_t sb = smem_u32(smem);
    const int tid = threadIdx.x;
    const int wid = tid >> 5, lane = tid & 31;
    const int wm = wid >> 2, wn = wid & 3;
    const int m0 = blockIdx.x * 128;

    if (tid < 128) *(float*)(smem + SM_BIAS + tid * 4) = bias[tid];

    float acc[4][4][4];
#pragma unroll
    for (int i = 0; i < 4; i++)
#pragma unroll
        for (int j = 0; j < 4; j++)
#pragma unroll
            for (int q = 0; q < 4; q++) acc[i][j][q] = 0.f;

    auto prefetch = [&](int s) {
        int k0 = c_K[s];
        const __nv_bfloat16* Bp = c_bHi[s] ? Bhi : Blo;
        uint32_t sB = sb + SM_B0 + (s & 1) * TILE_B;
#pragma unroll
        for (int t = 0; t < 4; t++) {
            int u = tid + t * 256;
            int row = u >> 3, f4 = u & 7;
            cp_async16(sB + SWZ128((uint32_t)(row * 128 + f4 * 16)),
                       Bp + (size_t)row * K2 + k0 + f4 * 8);
        }
        if (c_aNew[s]) {
            const __nv_bfloat16* Ap = c_aHi[s] ? g_Ahi : g_Alo;
            uint32_t sA = sb + SM_A0 + c_aBuf[s] * TILE_B;
#pragma unroll
            for (int t = 0; t < 4; t++) {
                int u = tid + t * 256;
                int row = u >> 3, f4 = u & 7;
                int gm = m0 + row;
                if (gm >= N_NODES) gm = N_NODES - 1;
                cp_async16(sA + SWZ128((uint32_t)(row * 128 + f4 * 16)),
                           Ap + (size_t)gm * K2 + k0 + f4 * 8);
            }
        }
    };

    prefetch(0);
    CP_COMMIT();

    for (int s = 0; s < 12; s++) {
        CP_WAIT0();
        __syncthreads();
        if (s + 1 < 12) { prefetch(s + 1); CP_COMMIT(); }

        uint32_t sA = sb + SM_A0 + c_aBuf[s] * TILE_B;
        uint32_t sB = sb + SM_B0 + (s & 1) * TILE_B;
#pragma unroll
        for (int kk = 0; kk < 4; kk++) {
            uint32_t a[4][4], b[4][2];
#pragma unroll
            for (int mf = 0; mf < 4; mf++) {
                int row  = wm * 64 + mf * 16 + (lane & 15);
                int colb = kk * 32 + (lane >> 4) * 16;
                ldsm_x4(a[mf], sA + SWZ128((uint32_t)(row * 128 + colb)));
            }
#pragma unroll
            for (int nh = 0; nh < 2; nh++) {
                uint32_t r[4];
                int row  = wn * 32 + nh * 16 + (lane & 7) + ((lane >> 4) << 3);
                int colb = kk * 32 + ((lane >> 3) & 1) * 16;
                ldsm_x4(r, sB + SWZ128((uint32_t)(row * 128 + colb)));
                b[nh * 2][0] = r[0]; b[nh * 2][1] = r[1];
                b[nh * 2 + 1][0] = r[2]; b[nh * 2 + 1][1] = r[3];
            }
#pragma unroll
            for (int mf = 0; mf < 4; mf++)
#pragma unroll
                for (int nf = 0; nf < 4; nf++)
                    mma_bf16(acc[mf][nf], a[mf], b[nf]);
        }
        __syncthreads();
    }

    // epilogue: bias + relu + store fp32 (+ optional next-layer bf16 hi/lo)
    const int qr = lane >> 2;
    const int qc = (lane & 3) * 2;
#pragma unroll
    for (int mf = 0; mf < 4; mf++) {
        int r0 = m0 + wm * 64 + mf * 16 + qr;
        int r1 = r0 + 8;
#pragma unroll
        for (int nf = 0; nf < 4; nf++) {
            int col = wn * 32 + nf * 8 + qc;
            float b0 = *(const float*)(smem + SM_BIAS + col * 4);
            float b1 = *(const float*)(smem + SM_BIAS + (col + 1) * 4);
            float v00 = fmaxf(acc[mf][nf][0] + b0, 0.f);
            float v01 = fmaxf(acc[mf][nf][1] + b1, 0.f);
            float v10 = fmaxf(acc[mf][nf][2] + b0, 0.f);
            float v11 = fmaxf(acc[mf][nf][3] + b1, 0.f);
            if (r0 < N_NODES) {
                *(float2*)(out + (size_t)r0 * D + col) = make_float2(v00, v01);
                if (write_next) {
                    __nv_bfloat16 h0 = __float2bfloat16(v00), h1 = __float2bfloat16(v01);
                    size_t off = (size_t)r0 * K2 + D + col;
                    *(uint32_t*)(nAhi + off) = pack2bf(v00, v01);
                    *(uint32_t*)(nAlo + off) = pack2bf(v00 - __bfloat162float(h0),
                                                       v01 - __bfloat162float(h1));
                }
            }
            if (r1 < N_NODES) {
                *(float2*)(out + (size_t)r1 * D + col) = make_float2(v10, v11);
                if (write_next) {
                    __nv_bfloat16 h0 = __float2bfloat16(v10), h1 = __float2bfloat16(v11);
                    size_t off = (size_t)r1 * K2 + D + col;
                    *(uint32_t*)(nAhi + off) = pack2bf(v10, v11);
                    *(uint32_t*)(nAlo + off) = pack2bf(v10 - __bfloat162float(h0),
                                                       v11 - __bfloat162float(h1));
                }
            }
        }
    }
}

// ================= launch ====================================================
extern "C" void kernel_launch(void* const* d_in, const int* in_sizes, int n_in,
                              void* d_out, int out_size) {
    const float* x  = (const float*)d_in[0];
    const void*  ei = d_in[1];
    const float* Wl1 = (const float*)d_in[2];
    const float* bl1 = (const float*)d_in[3];
    const float* Wr1 = (const float*)d_in[4];
    const float* Wl2 = (const float*)d_in[5];
    const float* bl2 = (const float*)d_in[6];
    const float* Wr2 = (const float*)d_in[7];
    const float* Wl3 = (const float*)d_in[8];
    const float* bl3 = (const float*)d_in[9];
    const float* Wr3 = (const float*)d_in[10];
    float* out = (float*)d_out;

    float *h1, *h2;
    __nv_bfloat16 *Ahi, *Alo, *Bhi, *Blo;
    cudaGetSymbolAddress((void**)&h1,  g_h1);
    cudaGetSymbolAddress((void**)&h2,  g_h2);
    cudaGetSymbolAddress((void**)&Ahi, g_Ahi);
    cudaGetSymbolAddress((void**)&Alo, g_Alo);
    cudaGetSymbolAddress((void**)&Bhi, g_Bhi);
    cudaGetSymbolAddress((void**)&Blo, g_Blo);

    cudaFuncSetAttribute(gemm_tc, cudaFuncAttributeMaxDynamicSharedMemorySize, SM_TOTAL);

    // prologue: 5 launches
    prep_all_kernel<<<K1_XB + K1_WB + K1_ZB, 256>>>(x, (const int*)ei,
                                                    Wl1, Wr1, Wl2, Wr2, Wl3, Wr3);
    count_kernel<<<(N_EDGES + 255) / 256, 256>>>(ei);
    scan_partial_kernel<<<NCHUNK, 1024>>>();
    scan_write_kernel<<<NCHUNK, 1024>>>();
    fill_kernel<<<(N_EDGES + 255) / 256, 256>>>(ei);

    const int AGG_GRID  = (N_NODES * 32 + 255) / 256;
    const int GEMM_GRID = (N_NODES + 127) / 128;   // 391

    // layer 1
    agg_kernel<<<AGG_GRID, 256>>>(x);
    gemm_tc<<<GEMM_GRID, 256, SM_TOTAL>>>(Bhi, Blo, bl1, h1, Ahi, Alo, 1);
    // layer 2
    agg_kernel<<<AGG_GRID, 256>>>(h1);
    gemm_tc<<<GEMM_GRID, 256, SM_TOTAL>>>(Bhi + 128 * K2, Blo + 128 * K2,
                                          bl2, h2, Ahi, Alo, 1);
    // layer 3 -> final output
    agg_kernel<<<AGG_GRID, 256>>>(h2);
    gemm_tc<<<GEMM_GRID, 256, SM_TOTAL>>>(Bhi + 2 * 128 * K2, Blo + 2 * 128 * K2,
                                          bl3, out, (__nv_bfloat16*)nullptr,
                                          (__nv_bfloat16*)nullptr, 0);
}

// round 10
// speedup vs baseline: 3.6983x; 1.0502x over previous
#include <cuda_runtime.h>
#include <cuda_bf16.h>
#include <cstdint>

#define N_NODES 50000
#define N_EDGES 600000
#define D 128
#define K2 256             // concat [agg|h] K dimension
#define NCHUNK 49          // ceil(50000/1024)
#define GEMM_GRID 391      // ceil(50000/128)

// ================= helpers ===================================================
__device__ __forceinline__ uint32_t smem_u32(const void* p) {
    uint32_t a;
    asm("{ .reg .u64 t; cvta.to.shared.u64 t, %1; cvt.u32.u64 %0, t; }" : "=r"(a) : "l"(p));
    return a;
}
#define SWZ128(off) ((off) ^ (((off) >> 3) & 0x70))

__device__ __forceinline__ void ldsm_x4(uint32_t* r, uint32_t addr) {
    asm volatile("ldmatrix.sync.aligned.m8n8.x4.shared.b16 {%0,%1,%2,%3}, [%4];"
        : "=r"(r[0]), "=r"(r[1]), "=r"(r[2]), "=r"(r[3]) : "r"(addr));
}
__device__ __forceinline__ void mma_bf16(float* d, const uint32_t* a, const uint32_t* b) {
    asm volatile(
        "mma.sync.aligned.m16n8k16.row.col.f32.bf16.bf16.f32 "
        "{%0,%1,%2,%3}, {%4,%5,%6,%7}, {%8,%9}, {%0,%1,%2,%3};"
        : "+f"(d[0]), "+f"(d[1]), "+f"(d[2]), "+f"(d[3])
        : "r"(a[0]), "r"(a[1]), "r"(a[2]), "r"(a[3]), "r"(b[0]), "r"(b[1]));
}
__device__ __forceinline__ void cp_async16(uint32_t dst, const void* src) {
    asm volatile("cp.async.cg.shared.global [%0], [%1], 16;" :: "r"(dst), "l"(src));
}
#define CP_COMMIT() asm volatile("cp.async.commit_group;" ::: "memory")
#define CP_WAIT0()  asm volatile("cp.async.wait_group 0;" ::: "memory")

__device__ __forceinline__ uint32_t pack2bf(float a, float b) {
    __nv_bfloat162 t = __floats2bfloat162_rn(a, b);
    return *(uint32_t*)&t;
}

// ================ scratch (static device globals) ============================
__device__ int   g_is64;
__device__ int   g_cnt[N_NODES];
__device__ int   g_rowptr[N_NODES + 1];
__device__ int   g_cursor[N_NODES];
__device__ int   g_bsum[64];
__device__ int   g_srcidx[N_EDGES];
__device__ float g_h1[(size_t)N_NODES * D];
__device__ float g_h2[(size_t)N_NODES * D];
__device__ __nv_bfloat16 g_Ahi[(size_t)N_NODES * K2];   // cols [0,128)=agg, [128,256)=self
__device__ __nv_bfloat16 g_Alo[(size_t)N_NODES * K2];
__device__ __nv_bfloat16 g_Bhi[3 * 128 * K2];
__device__ __nv_bfloat16 g_Blo[3 * 128 * K2];

__device__ __forceinline__ int edge_val(const void* ei, int idx) {
    if (g_is64) return (int)((const long long*)ei)[idx];
    return ((const int*)ei)[idx];
}

// ================ prologue K1: xconv + weight prep + zero + detect ===========
#define K1_XB 6250
#define K1_WB 384
#define K1_ZB 196
__global__ __launch_bounds__(256)
void prep_all_kernel(const float* __restrict__ x, const int* __restrict__ ei32,
                     const float* __restrict__ Wl1, const float* __restrict__ Wr1,
                     const float* __restrict__ Wl2, const float* __restrict__ Wr2,
                     const float* __restrict__ Wl3, const float* __restrict__ Wr3) {
    int b = blockIdx.x;
    if (b < K1_XB) {
        int i = b * 256 + threadIdx.x;
        if (i >= N_NODES * 32) return;
        int row = i >> 5, c4 = i & 31;
        float4 v = *(const float4*)(x + (size_t)row * D + c4 * 4);
        __nv_bfloat16 h0 = __float2bfloat16(v.x), h1 = __float2bfloat16(v.y);
        __nv_bfloat16 h2 = __float2bfloat16(v.z), h3 = __float2bfloat16(v.w);
        uint2 hp, lp;
        hp.x = pack2bf(v.x, v.y); hp.y = pack2bf(v.z, v.w);
        lp.x = pack2bf(v.x - __bfloat162float(h0), v.y - __bfloat162float(h1));
        lp.y = pack2bf(v.z - __bfloat162float(h2), v.w - __bfloat162float(h3));
        size_t off = (size_t)row * K2 + D + c4 * 4;
        *(uint2*)(g_Ahi + off) = hp;
        *(uint2*)(g_Alo + off) = lp;
    } else if (b < K1_XB + K1_WB) {
        int i = (b - K1_XB) * 256 + threadIdx.x;   // < 98304
        int l = i / (128 * K2);
        int n = (i / K2) % 128;
        int k = i % K2;
        const float* Wl = (l == 0) ? Wl1 : (l == 1) ? Wl2 : Wl3;
        const float* Wr = (l == 0) ? Wr1 : (l == 1) ? Wr2 : Wr3;
        float v = (k < D) ? Wl[n * D + k] : Wr[n * D + (k - D)];
        __nv_bfloat16 hi = __float2bfloat16(v);
        g_Bhi[i] = hi;
        g_Blo[i] = __float2bfloat16(v - __bfloat162float(hi));
    } else {
        int i = (b - K1_XB - K1_WB) * 256 + threadIdx.x;
        if (i < N_NODES) g_cnt[i] = 0;
        if (i == 0) {
            int is64 = 1;
            for (int q = 0; q < 64; q++)
                if (ei32[2 * q + 1] != 0) { is64 = 0; break; }
            g_is64 = is64;
        }
    }
}

// ================ CSR build ==================================================
__global__ void count_kernel(const void* __restrict__ ei) {
    int e = blockIdx.x * blockDim.x + threadIdx.x;
    if (e < N_EDGES) atomicAdd(&g_cnt[edge_val(ei, N_EDGES + e)], 1);
}
__global__ void scan_partial_kernel() {
    __shared__ int s[1024];
    int i = blockIdx.x * 1024 + threadIdx.x;
    int v = (i < N_NODES) ? g_cnt[i] : 0;
    s[threadIdx.x] = v;
    __syncthreads();
    for (int off = 512; off > 0; off >>= 1) {
        if (threadIdx.x < off) s[threadIdx.x] += s[threadIdx.x + off];
        __syncthreads();
    }
    if (threadIdx.x == 0) g_bsum[blockIdx.x] = s[0];
}
__global__ void scan_write_kernel() {
    __shared__ int s[1024];
    __shared__ int pre[64];
    int i = blockIdx.x * 1024 + threadIdx.x;
    int v = (i < N_NODES) ? g_cnt[i] : 0;
    s[threadIdx.x] = v;
    if (threadIdx.x < 64)       // parallel prefix over <=49 block sums
        pre[threadIdx.x] = (threadIdx.x < blockIdx.x) ? g_bsum[threadIdx.x] : 0;
    __syncthreads();
    if (threadIdx.x < 32) {
        int t = pre[threadIdx.x] + pre[threadIdx.x + 32];
        for (int off = 16; off > 0; off >>= 1)
            t += __shfl_down_sync(0xFFFFFFFF, t, off);
        if (threadIdx.x == 0) pre[0] = t;
    }
    __syncthreads();
    int s_pre = pre[0];
    for (int off = 1; off < 1024; off <<= 1) {
        int t = (threadIdx.x >= off) ? s[threadIdx.x - off] : 0;
        __syncthreads();
        s[threadIdx.x] += t;
        __syncthreads();
    }
    if (i < N_NODES) {
        int excl = s[threadIdx.x] - v + s_pre;
        g_rowptr[i] = excl;
        g_cursor[i] = excl;
        if (i == N_NODES - 1) g_rowptr[N_NODES] = excl + v;
    }
}
__global__ void fill_kernel(const void* __restrict__ ei) {
    int e = blockIdx.x * blockDim.x + threadIdx.x;
    if (e < N_EDGES) {
        int d = edge_val(ei, N_EDGES + e);
        int s = edge_val(ei, e);
        g_srcidx[atomicAdd(&g_cursor[d], 1)] = s;
    }
}

// ===== mean aggregation (warp/node) -> bf16 hi/lo into A cols [0..128) =======
// Fires the PDL trigger immediately so the dependent GEMM can launch and run
// its self-feature chunks concurrently with this gather.
__global__ __launch_bounds__(256)
void agg_kernel(const float* __restrict__ h) {
    cudaTriggerProgrammaticLaunchCompletion();
    int warp = (blockIdx.x * blockDim.x + threadIdx.x) >> 5;
    int lane = threadIdx.x & 31;
    if (warp >= N_NODES) return;
    int beg = g_rowptr[warp];
    int end = g_rowptr[warp + 1];
    float4 s0 = make_float4(0.f,0.f,0.f,0.f), s1 = s0, s2 = s0, s3 = s0;
    int e = beg;
    for (; e + 4 <= end; e += 4) {
        int j0 = g_srcidx[e],     j1 = g_srcidx[e + 1];
        int j2 = g_srcidx[e + 2], j3 = g_srcidx[e + 3];
        float4 v0 = *(const float4*)(h + (size_t)j0 * D + lane * 4);
        float4 v1 = *(const float4*)(h + (size_t)j1 * D + lane * 4);
        float4 v2 = *(const float4*)(h + (size_t)j2 * D + lane * 4);
        float4 v3 = *(const float4*)(h + (size_t)j3 * D + lane * 4);
        s0.x += v0.x; s0.y += v0.y; s0.z += v0.z; s0.w += v0.w;
        s1.x += v1.x; s1.y += v1.y; s1.z += v1.z; s1.w += v1.w;
        s2.x += v2.x; s2.y += v2.y; s2.z += v2.z; s2.w += v2.w;
        s3.x += v3.x; s3.y += v3.y; s3.z += v3.z; s3.w += v3.w;
    }
    for (; e < end; e++) {
        int j = g_srcidx[e];
        float4 v = *(const float4*)(h + (size_t)j * D + lane * 4);
        s0.x += v.x; s0.y += v.y; s0.z += v.z; s0.w += v.w;
    }
    float inv = 1.0f / fmaxf((float)(end - beg), 1.0f);
    float4 m;
    m.x = ((s0.x + s1.x) + (s2.x + s3.x)) * inv;
    m.y = ((s0.y + s1.y) + (s2.y + s3.y)) * inv;
    m.z = ((s0.z + s1.z) + (s2.z + s3.z)) * inv;
    m.w = ((s0.w + s1.w) + (s2.w + s3.w)) * inv;
    __nv_bfloat16 h0 = __float2bfloat16(m.x), h1 = __float2bfloat16(m.y);
    __nv_bfloat16 h2 = __float2bfloat16(m.z), h3 = __float2bfloat16(m.w);
    uint2 hp, lp;
    hp.x = pack2bf(m.x, m.y); hp.y = pack2bf(m.z, m.w);
    lp.x = pack2bf(m.x - __bfloat162float(h0), m.y - __bfloat162float(h1));
    lp.y = pack2bf(m.z - __bfloat162float(h2), m.w - __bfloat162float(h3));
    size_t off = (size_t)warp * K2 + lane * 4;
    *(uint2*)(g_Ahi + off) = hp;
    *(uint2*)(g_Alo + off) = lp;
}

// ================= bf16 mma.sync GEMM (PDL secondary) ========================
// Chunks 0..5 touch only self cols [128,256) -> run before gridDepSync.
// Chunks 6..11 touch agg cols [0,128) -> gated by cudaGridDependencySynchronize.
//   s:      0        1        2        3        4        5
//      Ahi128*Bhi Ahi128*Blo Ahi192*Bhi Ahi192*Blo Alo128*Bhi Alo192*Bhi
//   s:      6        7        8        9       10       11
//      Ahi0*Bhi   Ahi0*Blo   Ahi64*Bhi  Ahi64*Blo  Alo0*Bhi   Alo64*Bhi
#define TILE_B  16384
#define SM_BIAS 0
#define SM_A0   1024
#define SM_B0   (1024 + 2 * TILE_B)
#define SM_TOTAL (1024 + 4 * TILE_B)   // 66560 -> 3 CTAs/SM

__constant__ int c_aNew[12] = {1,0,1,0,1,1, 1,0,1,0,1,1};
__constant__ int c_aBuf[12] = {0,0,1,1,0,1, 0,0,1,1,0,1};
__constant__ int c_aHi[12]  = {1,1,1,1,0,0, 1,1,1,1,0,0};
__constant__ int c_bHi[12]  = {1,0,1,0,1,1, 1,0,1,0,1,1};
__constant__ int c_K[12]    = {128,128,192,192,128,192, 0,0,64,64,0,64};

__global__ __launch_bounds__(256)
void gemm_tc(const __nv_bfloat16* __restrict__ Bhi, const __nv_bfloat16* __restrict__ Blo,
             const float* __restrict__ bias, float* __restrict__ out,
             __nv_bfloat16* __restrict__ nAhi, __nv_bfloat16* __restrict__ nAlo,
             int write_next) {
    extern __shared__ char smem[];
    const uint32_t sb = smem_u32(smem);
    const int tid = threadIdx.x;
    const int wid = tid >> 5, lane = tid & 31;
    const int wm = wid >> 2, wn = wid & 3;
    const int m0 = blockIdx.x * 128;

    if (tid < 128) *(float*)(smem + SM_BIAS + tid * 4) = bias[tid];

    float acc[4][4][4];
#pragma unroll
    for (int i = 0; i < 4; i++)
#pragma unroll
        for (int j = 0; j < 4; j++)
#pragma unroll
            for (int q = 0; q < 4; q++) acc[i][j][q] = 0.f;

    auto prefetch = [&](int s) {
        int k0 = c_K[s];
        const __nv_bfloat16* Bp = c_bHi[s] ? Bhi : Blo;
        uint32_t sB = sb + SM_B0 + (s & 1) * TILE_B;
#pragma unroll
        for (int t = 0; t < 4; t++) {
            int u = tid + t * 256;
            int row = u >> 3, f4 = u & 7;
            cp_async16(sB + SWZ128((uint32_t)(row * 128 + f4 * 16)),
                       Bp + (size_t)row * K2 + k0 + f4 * 8);
        }
        if (c_aNew[s]) {
            const __nv_bfloat16* Ap = c_aHi[s] ? g_Ahi : g_Alo;
            uint32_t sA = sb + SM_A0 + c_aBuf[s] * TILE_B;
#pragma unroll
            for (int t = 0; t < 4; t++) {
                int u = tid + t * 256;
                int row = u >> 3, f4 = u & 7;
                int gm = m0 + row;
                if (gm >= N_NODES) gm = N_NODES - 1;
                cp_async16(sA + SWZ128((uint32_t)(row * 128 + f4 * 16)),
                           Ap + (size_t)gm * K2 + k0 + f4 * 8);
            }
        }
    };

    prefetch(0);
    CP_COMMIT();

    for (int s = 0; s < 12; s++) {
        CP_WAIT0();
        __syncthreads();
        if (s + 1 == 6) cudaGridDependencySynchronize();   // agg cols ready
        if (s + 1 < 12) { prefetch(s + 1); CP_COMMIT(); }

        uint32_t sA = sb + SM_A0 + c_aBuf[s] * TILE_B;
        uint32_t sB = sb + SM_B0 + (s & 1) * TILE_B;
#pragma unroll
        for (int kk = 0; kk < 4; kk++) {
            uint32_t a[4][4], b[4][2];
#pragma unroll
            for (int mf = 0; mf < 4; mf++) {
                int row  = wm * 64 + mf * 16 + (lane & 15);
                int colb = kk * 32 + (lane >> 4) * 16;
                ldsm_x4(a[mf], sA + SWZ128((uint32_t)(row * 128 + colb)));
            }
#pragma unroll
            for (int nh = 0; nh < 2; nh++) {
                uint32_t r[4];
                int row  = wn * 32 + nh * 16 + (lane & 7) + ((lane >> 4) << 3);
                int colb = kk * 32 + ((lane >> 3) & 1) * 16;
                ldsm_x4(r, sB + SWZ128((uint32_t)(row * 128 + colb)));
                b[nh * 2][0] = r[0]; b[nh * 2][1] = r[1];
                b[nh * 2 + 1][0] = r[2]; b[nh * 2 + 1][1] = r[3];
            }
#pragma unroll
            for (int mf = 0; mf < 4; mf++)
#pragma unroll
                for (int nf = 0; nf < 4; nf++)
                    mma_bf16(acc[mf][nf], a[mf], b[nf]);
        }
        __syncthreads();
    }

    // epilogue: bias + relu + store fp32 (+ optional next-layer bf16 hi/lo)
    const int qr = lane >> 2;
    const int qc = (lane & 3) * 2;
#pragma unroll
    for (int mf = 0; mf < 4; mf++) {
        int r0 = m0 + wm * 64 + mf * 16 + qr;
        int r1 = r0 + 8;
#pragma unroll
        for (int nf = 0; nf < 4; nf++) {
            int col = wn * 32 + nf * 8 + qc;
            float b0 = *(const float*)(smem + SM_BIAS + col * 4);
            float b1 = *(const float*)(smem + SM_BIAS + (col + 1) * 4);
            float v00 = fmaxf(acc[mf][nf][0] + b0, 0.f);
            float v01 = fmaxf(acc[mf][nf][1] + b1, 0.f);
            float v10 = fmaxf(acc[mf][nf][2] + b0, 0.f);
            float v11 = fmaxf(acc[mf][nf][3] + b1, 0.f);
            if (r0 < N_NODES) {
                *(float2*)(out + (size_t)r0 * D + col) = make_float2(v00, v01);
                if (write_next) {
                    __nv_bfloat16 h0 = __float2bfloat16(v00), h1 = __float2bfloat16(v01);
                    size_t off = (size_t)r0 * K2 + D + col;
                    *(uint32_t*)(nAhi + off) = pack2bf(v00, v01);
                    *(uint32_t*)(nAlo + off) = pack2bf(v00 - __bfloat162float(h0),
                                                       v01 - __bfloat162float(h1));
                }
            }
            if (r1 < N_NODES) {
                *(float2*)(out + (size_t)r1 * D + col) = make_float2(v10, v11);
                if (write_next) {
                    __nv_bfloat16 h0 = __float2bfloat16(v10), h1 = __float2bfloat16(v11);
                    size_t off = (size_t)r1 * K2 + D + col;
                    *(uint32_t*)(nAhi + off) = pack2bf(v10, v11);
                    *(uint32_t*)(nAlo + off) = pack2bf(v10 - __bfloat162float(h0),
                                                       v11 - __bfloat162float(h1));
                }
            }
        }
    }
}

// ================= launch ====================================================
static void launch_gemm_pdl(const __nv_bfloat16* Bhi, const __nv_bfloat16* Blo,
                            const float* bias, float* out,
                            __nv_bfloat16* nAhi, __nv_bfloat16* nAlo, int write_next) {
    cudaLaunchConfig_t cfg = {};
    cfg.gridDim = dim3(GEMM_GRID);
    cfg.blockDim = dim3(256);
    cfg.dynamicSmemBytes = SM_TOTAL;
    cfg.stream = 0;
    cudaLaunchAttribute at[1];
    at[0].id = cudaLaunchAttributeProgrammaticStreamSerialization;
    at[0].val.programmaticStreamSerializationAllowed = 1;
    cfg.attrs = at;
    cfg.numAttrs = 1;
    cudaLaunchKernelEx(&cfg, gemm_tc, Bhi, Blo, bias, out, nAhi, nAlo, write_next);
}

extern "C" void kernel_launch(void* const* d_in, const int* in_sizes, int n_in,
                              void* d_out, int out_size) {
    const float* x  = (const float*)d_in[0];
    const void*  ei = d_in[1];
    const float* Wl1 = (const float*)d_in[2];
    const float* bl1 = (const float*)d_in[3];
    const float* Wr1 = (const float*)d_in[4];
    const float* Wl2 = (const float*)d_in[5];
    const float* bl2 = (const float*)d_in[6];
    const float* Wr2 = (const float*)d_in[7];
    const float* Wl3 = (const float*)d_in[8];
    const float* bl3 = (const float*)d_in[9];
    const float* Wr3 = (const float*)d_in[10];
    float* out = (float*)d_out;

    float *h1, *h2;
    __nv_bfloat16 *Ahi, *Alo, *Bhi, *Blo;
    cudaGetSymbolAddress((void**)&h1,  g_h1);
    cudaGetSymbolAddress((void**)&h2,  g_h2);
    cudaGetSymbolAddress((void**)&Ahi, g_Ahi);
    cudaGetSymbolAddress((void**)&Alo, g_Alo);
    cudaGetSymbolAddress((void**)&Bhi, g_Bhi);
    cudaGetSymbolAddress((void**)&Blo, g_Blo);

    cudaFuncSetAttribute(gemm_tc, cudaFuncAttributeMaxDynamicSharedMemorySize, SM_TOTAL);

    // prologue
    prep_all_kernel<<<K1_XB + K1_WB + K1_ZB, 256>>>(x, (const int*)ei,
                                                    Wl1, Wr1, Wl2, Wr2, Wl3, Wr3);
    count_kernel<<<(N_EDGES + 255) / 256, 256>>>(ei);
    scan_partial_kernel<<<NCHUNK, 1024>>>();
    scan_write_kernel<<<NCHUNK, 1024>>>();
    fill_kernel<<<(N_EDGES + 255) / 256, 256>>>(ei);

    const int AGG_GRID = (N_NODES * 32 + 255) / 256;

    // layer 1 (agg triggers early; gemm overlaps its self chunks with agg)
    agg_kernel<<<AGG_GRID, 256>>>(x);
    launch_gemm_pdl(Bhi, Blo, bl1, h1, Ahi, Alo, 1);
    // layer 2
    agg_kernel<<<AGG_GRID, 256>>>(h1);
    launch_gemm_pdl(Bhi + 128 * K2, Blo + 128 * K2, bl2, h2, Ahi, Alo, 1);
    // layer 3 -> final output
    agg_kernel<<<AGG_GRID, 256>>>(h2);
    launch_gemm_pdl(Bhi + 2 * 128 * K2, Blo + 2 * 128 * K2, bl3, out,
                    (__nv_bfloat16*)nullptr, (__nv_bfloat16*)nullptr, 0);
}

// round 12
// speedup vs baseline: 3.8794x; 1.0490x over previous
#include <cuda_runtime.h>
#include <cuda_bf16.h>
#include <cuda_fp16.h>
#include <cstdint>

#define N_NODES 50000
#define N_EDGES 600000
#define D 128
#define K2 256             // concat [agg|h] K dimension
#define NCHUNK 49          // ceil(50000/1024)
#define GEMM_GRID 391      // ceil(50000/128)

// ================= helpers ===================================================
__device__ __forceinline__ uint32_t smem_u32(const void* p) {
    uint32_t a;
    asm("{ .reg .u64 t; cvta.to.shared.u64 t, %1; cvt.u32.u64 %0, t; }" : "=r"(a) : "l"(p));
    return a;
}
#define SWZ128(off) ((off) ^ (((off) >> 3) & 0x70))

__device__ __forceinline__ void ldsm_x4(uint32_t* r, uint32_t addr) {
    asm volatile("ldmatrix.sync.aligned.m8n8.x4.shared.b16 {%0,%1,%2,%3}, [%4];"
        : "=r"(r[0]), "=r"(r[1]), "=r"(r[2]), "=r"(r[3]) : "r"(addr));
}
__device__ __forceinline__ void mma_bf16(float* d, const uint32_t* a, const uint32_t* b) {
    asm volatile(
        "mma.sync.aligned.m16n8k16.row.col.f32.bf16.bf16.f32 "
        "{%0,%1,%2,%3}, {%4,%5,%6,%7}, {%8,%9}, {%0,%1,%2,%3};"
        : "+f"(d[0]), "+f"(d[1]), "+f"(d[2]), "+f"(d[3])
        : "r"(a[0]), "r"(a[1]), "r"(a[2]), "r"(a[3]), "r"(b[0]), "r"(b[1]));
}
__device__ __forceinline__ void cp_async16(uint32_t dst, const void* src) {
    asm volatile("cp.async.cg.shared.global [%0], [%1], 16;" :: "r"(dst), "l"(src));
}
#define CP_COMMIT() asm volatile("cp.async.commit_group;" ::: "memory")
#define CP_WAIT0()  asm volatile("cp.async.wait_group 0;" ::: "memory")

__device__ __forceinline__ uint32_t pack2bf(float a, float b) {
    __nv_bfloat162 t = __floats2bfloat162_rn(a, b);
    return *(uint32_t*)&t;
}
__device__ __forceinline__ uint32_t pack2hf(float a, float b) {
    __half2 t = __floats2half2_rn(a, b);
    return *(uint32_t*)&t;
}

// ================ scratch (static device globals) ============================
__device__ int   g_is64;
__device__ int   g_cnt[N_NODES];
__device__ int   g_rowptr[N_NODES + 1];
__device__ int   g_cursor[N_NODES];
__device__ int   g_bsum[64];
__device__ int   g_srcidx[N_EDGES];
__device__ __half g_hf16[(size_t)N_NODES * D];          // fp16 gather source
__device__ __nv_bfloat16 g_Ahi[(size_t)N_NODES * K2];   // cols [0,128)=agg, [128,256)=self
__device__ __nv_bfloat16 g_Alo[(size_t)N_NODES * K2];
__device__ __nv_bfloat16 g_Bhi[3 * 128 * K2];
__device__ __nv_bfloat16 g_Blo[3 * 128 * K2];

__device__ __forceinline__ int edge_val(const void* ei, int idx) {
    if (g_is64) return (int)((const long long*)ei)[idx];
    return ((const int*)ei)[idx];
}

// ================ prologue K1: xconv + weight prep + zero + detect ===========
#define K1_XB 6250
#define K1_WB 384
#define K1_ZB 196
__global__ __launch_bounds__(256)
void prep_all_kernel(const float* __restrict__ x, const int* __restrict__ ei32,
                     const float* __restrict__ Wl1, const float* __restrict__ Wr1,
                     const float* __restrict__ Wl2, const float* __restrict__ Wr2,
                     const float* __restrict__ Wl3, const float* __restrict__ Wr3) {
    int b = blockIdx.x;
    if (b < K1_XB) {
        int i = b * 256 + threadIdx.x;
        if (i >= N_NODES * 32) return;
        int row = i >> 5, c4 = i & 31;
        float4 v = *(const float4*)(x + (size_t)row * D + c4 * 4);
        __nv_bfloat16 h0 = __float2bfloat16(v.x), h1 = __float2bfloat16(v.y);
        __nv_bfloat16 h2 = __float2bfloat16(v.z), h3 = __float2bfloat16(v.w);
        uint2 hp, lp, fp;
        hp.x = pack2bf(v.x, v.y); hp.y = pack2bf(v.z, v.w);
        lp.x = pack2bf(v.x - __bfloat162float(h0), v.y - __bfloat162float(h1));
        lp.y = pack2bf(v.z - __bfloat162float(h2), v.w - __bfloat162float(h3));
        fp.x = pack2hf(v.x, v.y); fp.y = pack2hf(v.z, v.w);
        size_t off = (size_t)row * K2 + D + c4 * 4;
        *(uint2*)(g_Ahi + off) = hp;
        *(uint2*)(g_Alo + off) = lp;
        *(uint2*)(g_hf16 + (size_t)row * D + c4 * 4) = fp;
    } else if (b < K1_XB + K1_WB) {
        int i = (b - K1_XB) * 256 + threadIdx.x;   // < 98304
        int l = i / (128 * K2);
        int n = (i / K2) % 128;
        int k = i % K2;
        const float* Wl = (l == 0) ? Wl1 : (l == 1) ? Wl2 : Wl3;
        const float* Wr = (l == 0) ? Wr1 : (l == 1) ? Wr2 : Wr3;
        float v = (k < D) ? Wl[n * D + k] : Wr[n * D + (k - D)];
        __nv_bfloat16 hi = __float2bfloat16(v);
        g_Bhi[i] = hi;
        g_Blo[i] = __float2bfloat16(v - __bfloat162float(hi));
    } else {
        int i = (b - K1_XB - K1_WB) * 256 + threadIdx.x;
        if (i < N_NODES) g_cnt[i] = 0;
        if (i == 0) {
            int is64 = 1;
            for (int q = 0; q < 64; q++)
                if (ei32[2 * q + 1] != 0) { is64 = 0; break; }
            g_is64 = is64;
        }
    }
}

// ================ CSR build ==================================================
__global__ void count_kernel(const void* __restrict__ ei) {
    int e = blockIdx.x * blockDim.x + threadIdx.x;
    if (e < N_EDGES) atomicAdd(&g_cnt[edge_val(ei, N_EDGES + e)], 1);
}
__global__ void scan_partial_kernel() {
    __shared__ int s[1024];
    int i = blockIdx.x * 1024 + threadIdx.x;
    int v = (i < N_NODES) ? g_cnt[i] : 0;
    s[threadIdx.x] = v;
    __syncthreads();
    for (int off = 512; off > 0; off >>= 1) {
        if (threadIdx.x < off) s[threadIdx.x] += s[threadIdx.x + off];
        __syncthreads();
    }
    if (threadIdx.x == 0) g_bsum[blockIdx.x] = s[0];
}
__global__ void scan_write_kernel() {
    __shared__ int s[1024];
    __shared__ int pre[64];
    int i = blockIdx.x * 1024 + threadIdx.x;
    int v = (i < N_NODES) ? g_cnt[i] : 0;
    s[threadIdx.x] = v;
    if (threadIdx.x < 64)
        pre[threadIdx.x] = (threadIdx.x < blockIdx.x) ? g_bsum[threadIdx.x] : 0;
    __syncthreads();
    if (threadIdx.x < 32) {
        int t = pre[threadIdx.x] + pre[threadIdx.x + 32];
        for (int off = 16; off > 0; off >>= 1)
            t += __shfl_down_sync(0xFFFFFFFF, t, off);
        if (threadIdx.x == 0) pre[0] = t;
    }
    __syncthreads();
    int s_pre = pre[0];
    for (int off = 1; off < 1024; off <<= 1) {
        int t = (threadIdx.x >= off) ? s[threadIdx.x - off] : 0;
        __syncthreads();
        s[threadIdx.x] += t;
        __syncthreads();
    }
    if (i < N_NODES) {
        int excl = s[threadIdx.x] - v + s_pre;
        g_rowptr[i] = excl;
        g_cursor[i] = excl;
        if (i == N_NODES - 1) g_rowptr[N_NODES] = excl + v;
    }
}
__global__ void fill_kernel(const void* __restrict__ ei) {
    int e = blockIdx.x * blockDim.x + threadIdx.x;
    if (e < N_EDGES) {
        int d = edge_val(ei, N_EDGES + e);
        int s = edge_val(ei, e);
        g_srcidx[atomicAdd(&g_cursor[d], 1)] = s;
    }
}

// ===== mean aggregation (warp/node, fp16 gather) -> bf16 hi/lo A cols [0,128)
__global__ __launch_bounds__(256)
void agg_kernel() {
    cudaTriggerProgrammaticLaunchCompletion();
    int warp = (blockIdx.x * blockDim.x + threadIdx.x) >> 5;
    int lane = threadIdx.x & 31;
    if (warp >= N_NODES) return;
    int beg = g_rowptr[warp];
    int end = g_rowptr[warp + 1];
    float4 s0 = make_float4(0.f,0.f,0.f,0.f), s1 = s0, s2 = s0, s3 = s0;
    const __half* hp16 = g_hf16;
    int e = beg;
    for (; e + 4 <= end; e += 4) {
        int j0 = g_srcidx[e],     j1 = g_srcidx[e + 1];
        int j2 = g_srcidx[e + 2], j3 = g_srcidx[e + 3];
        uint2 r0 = *(const uint2*)(hp16 + (size_t)j0 * D + lane * 4);
        uint2 r1 = *(const uint2*)(hp16 + (size_t)j1 * D + lane * 4);
        uint2 r2 = *(const uint2*)(hp16 + (size_t)j2 * D + lane * 4);
        uint2 r3 = *(const uint2*)(hp16 + (size_t)j3 * D + lane * 4);
        float2 a0 = __half22float2(*(__half2*)&r0.x), b0 = __half22float2(*(__half2*)&r0.y);
        float2 a1 = __half22float2(*(__half2*)&r1.x), b1 = __half22float2(*(__half2*)&r1.y);
        float2 a2 = __half22float2(*(__half2*)&r2.x), b2 = __half22float2(*(__half2*)&r2.y);
        float2 a3 = __half22float2(*(__half2*)&r3.x), b3 = __half22float2(*(__half2*)&r3.y);
        s0.x += a0.x; s0.y += a0.y; s0.z += b0.x; s0.w += b0.y;
        s1.x += a1.x; s1.y += a1.y; s1.z += b1.x; s1.w += b1.y;
        s2.x += a2.x; s2.y += a2.y; s2.z += b2.x; s2.w += b2.y;
        s3.x += a3.x; s3.y += a3.y; s3.z += b3.x; s3.w += b3.y;
    }
    for (; e < end; e++) {
        int j = g_srcidx[e];
        uint2 r = *(const uint2*)(hp16 + (size_t)j * D + lane * 4);
        float2 a = __half22float2(*(__half2*)&r.x), b = __half22float2(*(__half2*)&r.y);
        s0.x += a.x; s0.y += a.y; s0.z += b.x; s0.w += b.y;
    }
    float inv = 1.0f / fmaxf((float)(end - beg), 1.0f);
    float4 m;
    m.x = ((s0.x + s1.x) + (s2.x + s3.x)) * inv;
    m.y = ((s0.y + s1.y) + (s2.y + s3.y)) * inv;
    m.z = ((s0.z + s1.z) + (s2.z + s3.z)) * inv;
    m.w = ((s0.w + s1.w) + (s2.w + s3.w)) * inv;
    __nv_bfloat16 h0 = __float2bfloat16(m.x), h1 = __float2bfloat16(m.y);
    __nv_bfloat16 h2 = __float2bfloat16(m.z), h3 = __float2bfloat16(m.w);
    uint2 hp, lp;
    hp.x = pack2bf(m.x, m.y); hp.y = pack2bf(m.z, m.w);
    lp.x = pack2bf(m.x - __bfloat162float(h0), m.y - __bfloat162float(h1));
    lp.y = pack2bf(m.z - __bfloat162float(h2), m.w - __bfloat162float(h3));
    size_t off = (size_t)warp * K2 + lane * 4;
    *(uint2*)(g_Ahi + off) = hp;
    *(uint2*)(g_Alo + off) = lp;
}

// ================= bf16 mma.sync GEMM (PDL secondary) ========================
// Chunks 0..5: self cols [128,256) (pre-gridDepSync); 6..11: agg cols [0,128).
#define TILE_B  16384
#define SM_BIAS 0
#define SM_A0   1024
#define SM_B0   (1024 + 2 * TILE_B)
#define SM_TOTAL (1024 + 4 * TILE_B)   // 66560 -> 3 CTAs/SM

__constant__ int c_aNew[12] = {1,0,1,0,1,1, 1,0,1,0,1,1};
__constant__ int c_aBuf[12] = {0,0,1,1,0,1, 0,0,1,1,0,1};
__constant__ int c_aHi[12]  = {1,1,1,1,0,0, 1,1,1,1,0,0};
__constant__ int c_bHi[12]  = {1,0,1,0,1,1, 1,0,1,0,1,1};
__constant__ int c_K[12]    = {128,128,192,192,128,192, 0,0,64,64,0,64};

__global__ __launch_bounds__(256)
void gemm_tc(const __nv_bfloat16* __restrict__ Bhi, const __nv_bfloat16* __restrict__ Blo,
             const float* __restrict__ bias, float* __restrict__ out,
             int write_next) {
    extern __shared__ char smem[];
    const uint32_t sb = smem_u32(smem);
    const int tid = threadIdx.x;
    const int wid = tid >> 5, lane = tid & 31;
    const int wm = wid >> 2, wn = wid & 3;
    const int m0 = blockIdx.x * 128;

    if (tid < 128) *(float*)(smem + SM_BIAS + tid * 4) = bias[tid];

    float acc[4][4][4];
#pragma unroll
    for (int i = 0; i < 4; i++)
#pragma unroll
        for (int j = 0; j < 4; j++)
#pragma unroll
            for (int q = 0; q < 4; q++) acc[i][j][q] = 0.f;

    auto prefetch = [&](int s) {
        int k0 = c_K[s];
        const __nv_bfloat16* Bp = c_bHi[s] ? Bhi : Blo;
        uint32_t sB = sb + SM_B0 + (s & 1) * TILE_B;
#pragma unroll
        for (int t = 0; t < 4; t++) {
            int u = tid + t * 256;
            int row = u >> 3, f4 = u & 7;
            cp_async16(sB + SWZ128((uint32_t)(row * 128 + f4 * 16)),
                       Bp + (size_t)row * K2 + k0 + f4 * 8);
        }
        if (c_aNew[s]) {
            const __nv_bfloat16* Ap = c_aHi[s] ? g_Ahi : g_Alo;
            uint32_t sA = sb + SM_A0 + c_aBuf[s] * TILE_B;
#pragma unroll
            for (int t = 0; t < 4; t++) {
                int u = tid + t * 256;
                int row = u >> 3, f4 = u & 7;
                int gm = m0 + row;
                if (gm >= N_NODES) gm = N_NODES - 1;
                cp_async16(sA + SWZ128((uint32_t)(row * 128 + f4 * 16)),
                           Ap + (size_t)gm * K2 + k0 + f4 * 8);
            }
        }
    };

    prefetch(0);
    CP_COMMIT();

    for (int s = 0; s < 12; s++) {
        CP_WAIT0();
        __syncthreads();
        if (s + 1 == 6) cudaGridDependencySynchronize();   // agg cols ready
        if (s + 1 < 12) { prefetch(s + 1); CP_COMMIT(); }

        uint32_t sA = sb + SM_A0 + c_aBuf[s] * TILE_B;
        uint32_t sB = sb + SM_B0 + (s & 1) * TILE_B;
#pragma unroll
        for (int kk = 0; kk < 4; kk++) {
            uint32_t a[4][4], b[4][2];
#pragma unroll
            for (int mf = 0; mf < 4; mf++) {
                int row  = wm * 64 + mf * 16 + (lane & 15);
                int colb = kk * 32 + (lane >> 4) * 16;
                ldsm_x4(a[mf], sA + SWZ128((uint32_t)(row * 128 + colb)));
            }
#pragma unroll
            for (int nh = 0; nh < 2; nh++) {
                uint32_t r[4];
                int row  = wn * 32 + nh * 16 + (lane & 7) + ((lane >> 4) << 3);
                int colb = kk * 32 + ((lane >> 3) & 1) * 16;
                ldsm_x4(r, sB + SWZ128((uint32_t)(row * 128 + colb)));
                b[nh * 2][0] = r[0]; b[nh * 2][1] = r[1];
                b[nh * 2 + 1][0] = r[2]; b[nh * 2 + 1][1] = r[3];
            }
#pragma unroll
            for (int mf = 0; mf < 4; mf++)
#pragma unroll
                for (int nf = 0; nf < 4; nf++)
                    mma_bf16(acc[mf][nf], a[mf], b[nf]);
        }
        __syncthreads();
    }

    // epilogue: bias + relu.
    // write_next: fp16 gather copy + bf16 hi/lo self cols (no fp32 store).
    // final:      fp32 out only.
    const int qr = lane >> 2;
    const int qc = (lane & 3) * 2;
#pragma unroll
    for (int mf = 0; mf < 4; mf++) {
        int r0 = m0 + wm * 64 + mf * 16 + qr;
        int r1 = r0 + 8;
#pragma unroll
        for (int nf = 0; nf < 4; nf++) {
            int col = wn * 32 + nf * 8 + qc;
            float b0 = *(const float*)(smem + SM_BIAS + col * 4);
            float b1 = *(const float*)(smem + SM_BIAS + (col + 1) * 4);
            float v00 = fmaxf(acc[mf][nf][0] + b0, 0.f);
            float v01 = fmaxf(acc[mf][nf][1] + b1, 0.f);
            float v10 = fmaxf(acc[mf][nf][2] + b0, 0.f);
            float v11 = fmaxf(acc[mf][nf][3] + b1, 0.f);
            if (r0 < N_NODES) {
                if (write_next) {
                    __nv_bfloat16 h0 = __float2bfloat16(v00), h1 = __float2bfloat16(v01);
                    size_t off = (size_t)r0 * K2 + D + col;
                    *(uint32_t*)(g_Ahi + off) = pack2bf(v00, v01);
                    *(uint32_t*)(g_Alo + off) = pack2bf(v00 - __bfloat162float(h0),
                                                        v01 - __bfloat162float(h1));
                    *(uint32_t*)(g_hf16 + (size_t)r0 * D + col) = pack2hf(v00, v01);
                } else {
                    *(float2*)(out + (size_t)r0 * D + col) = make_float2(v00, v01);
                }
            }
            if (r1 < N_NODES) {
                if (write_next) {
                    __nv_bfloat16 h0 = __float2bfloat16(v10), h1 = __float2bfloat16(v11);
                    size_t off = (size_t)r1 * K2 + D + col;
                    *(uint32_t*)(g_Ahi + off) = pack2bf(v10, v11);
                    *(uint32_t*)(g_Alo + off) = pack2bf(v10 - __bfloat162float(h0),
                                                        v11 - __bfloat162float(h1));
                    *(uint32_t*)(g_hf16 + (size_t)r1 * D + col) = pack2hf(v10, v11);
                } else {
                    *(float2*)(out + (size_t)r1 * D + col) = make_float2(v10, v11);
                }
            }
        }
    }
}

// ================= launch ====================================================
static void launch_gemm_pdl(const __nv_bfloat16* Bhi, const __nv_bfloat16* Blo,
                            const float* bias, float* out, int write_next) {
    cudaLaunchConfig_t cfg = {};
    cfg.gridDim = dim3(GEMM_GRID);
    cfg.blockDim = dim3(256);
    cfg.dynamicSmemBytes = SM_TOTAL;
    cfg.stream = 0;
    cudaLaunchAttribute at[1];
    at[0].id = cudaLaunchAttributeProgrammaticStreamSerialization;
    at[0].val.programmaticStreamSerializationAllowed = 1;
    cfg.attrs = at;
    cfg.numAttrs = 1;
    cudaLaunchKernelEx(&cfg, gemm_tc, Bhi, Blo, bias, out, write_next);
}

extern "C" void kernel_launch(void* const* d_in, const int* in_sizes, int n_in,
                              void* d_out, int out_size) {
    const float* x  = (const float*)d_in[0];
    const void*  ei = d_in[1];
    const float* Wl1 = (const float*)d_in[2];
    const float* bl1 = (const float*)d_in[3];
    const float* Wr1 = (const float*)d_in[4];
    const float* Wl2 = (const float*)d_in[5];
    const float* bl2 = (const float*)d_in[6];
    const float* Wr2 = (const float*)d_in[7];
    const float* Wl3 = (const float*)d_in[8];
    const float* bl3 = (const float*)d_in[9];
    const float* Wr3 = (const float*)d_in[10];
    float* out = (float*)d_out;

    __nv_bfloat16 *Bhi, *Blo;
    cudaGetSymbolAddress((void**)&Bhi, g_Bhi);
    cudaGetSymbolAddress((void**)&Blo, g_Blo);

    cudaFuncSetAttribute(gemm_tc, cudaFuncAttributeMaxDynamicSharedMemorySize, SM_TOTAL);

    // prologue
    prep_all_kernel<<<K1_XB + K1_WB + K1_ZB, 256>>>(x, (const int*)ei,
                                                    Wl1, Wr1, Wl2, Wr2, Wl3, Wr3);
    count_kernel<<<(N_EDGES + 255) / 256, 256>>>(ei);
    scan_partial_kernel<<<NCHUNK, 1024>>>();
    scan_write_kernel<<<NCHUNK, 1024>>>();
    fill_kernel<<<(N_EDGES + 255) / 256, 256>>>(ei);

    const int AGG_GRID = (N_NODES * 32 + 255) / 256;

    // layer 1 (agg triggers early; gemm overlaps self chunks with the gather)
    agg_kernel<<<AGG_GRID, 256>>>();
    launch_gemm_pdl(Bhi, Blo, bl1, nullptr, 1);
    // layer 2
    agg_kernel<<<AGG_GRID, 256>>>();
    launch_gemm_pdl(Bhi + 128 * K2, Blo + 128 * K2, bl2, nullptr, 1);
    // layer 3 -> final output
    agg_kernel<<<AGG_GRID, 256>>>();
    launch_gemm_pdl(Bhi + 2 * 128 * K2, Blo + 2 * 128 * K2, bl3, out, 0);
}

// round 13
// speedup vs baseline: 4.0156x; 1.0351x over previous
#include <cuda_runtime.h>
#include <cuda_bf16.h>
#include <cuda_fp16.h>
#include <cstdint>

#define N_NODES 50000
#define N_EDGES 600000
#define D 128
#define K2 256             // concat [agg|h] K dimension
#define NCHUNK 49          // ceil(50000/1024)
#define GEMM_GRID 391      // ceil(50000/128)

// ================= helpers ===================================================
__device__ __forceinline__ uint32_t smem_u32(const void* p) {
    uint32_t a;
    asm("{ .reg .u64 t; cvta.to.shared.u64 t, %1; cvt.u32.u64 %0, t; }" : "=r"(a) : "l"(p));
    return a;
}
#define SWZ128(off) ((off) ^ (((off) >> 3) & 0x70))

__device__ __forceinline__ void ldsm_x4(uint32_t* r, uint32_t addr) {
    asm volatile("ldmatrix.sync.aligned.m8n8.x4.shared.b16 {%0,%1,%2,%3}, [%4];"
        : "=r"(r[0]), "=r"(r[1]), "=r"(r[2]), "=r"(r[3]) : "r"(addr));
}
__device__ __forceinline__ void mma_bf16(float* d, const uint32_t* a, const uint32_t* b) {
    asm volatile(
        "mma.sync.aligned.m16n8k16.row.col.f32.bf16.bf16.f32 "
        "{%0,%1,%2,%3}, {%4,%5,%6,%7}, {%8,%9}, {%0,%1,%2,%3};"
        : "+f"(d[0]), "+f"(d[1]), "+f"(d[2]), "+f"(d[3])
        : "r"(a[0]), "r"(a[1]), "r"(a[2]), "r"(a[3]), "r"(b[0]), "r"(b[1]));
}
__device__ __forceinline__ void cp_async16(uint32_t dst, const void* src) {
    asm volatile("cp.async.cg.shared.global [%0], [%1], 16;" :: "r"(dst), "l"(src));
}
#define CP_COMMIT() asm volatile("cp.async.commit_group;" ::: "memory")
#define CP_WAIT0()  asm volatile("cp.async.wait_group 0;" ::: "memory")

__device__ __forceinline__ uint32_t pack2bf(float a, float b) {
    __nv_bfloat162 t = __floats2bfloat162_rn(a, b);
    return *(uint32_t*)&t;
}
__device__ __forceinline__ uint32_t pack2hf(float a, float b) {
    __half2 t = __floats2half2_rn(a, b);
    return *(uint32_t*)&t;
}

// ================ scratch (static device globals) ============================
__device__ int   g_is64;
__device__ int   g_cnt[N_NODES];
__device__ int   g_rowptr[N_NODES + 1];
__device__ int   g_cursor[N_NODES];
__device__ int   g_bsum[64];
__device__ int   g_srcidx[N_EDGES];
__device__ __half g_hf16[(size_t)N_NODES * D];          // fp16 gather source
__device__ __nv_bfloat16 g_Ahi[(size_t)N_NODES * K2];   // cols [0,128)=agg, [128,256)=self
__device__ __nv_bfloat16 g_Alo[(size_t)N_NODES * K2];
__device__ __nv_bfloat16 g_Bhi[3 * 128 * K2];
__device__ __nv_bfloat16 g_Blo[3 * 128 * K2];

__device__ __forceinline__ int edge_val(const void* ei, int idx) {
    if (g_is64) return (int)((const long long*)ei)[idx];
    return ((const int*)ei)[idx];
}

// ================ prologue K1: xconv + weight prep + zero + detect ===========
#define K1_XB 6250
#define K1_WB 384
#define K1_ZB 196
__global__ __launch_bounds__(256)
void prep_all_kernel(const float* __restrict__ x, const int* __restrict__ ei32,
                     const float* __restrict__ Wl1, const float* __restrict__ Wr1,
                     const float* __restrict__ Wl2, const float* __restrict__ Wr2,
                     const float* __restrict__ Wl3, const float* __restrict__ Wr3) {
    cudaTriggerProgrammaticLaunchCompletion();
    int b = blockIdx.x;
    if (b < K1_XB) {
        int i = b * 256 + threadIdx.x;
        if (i >= N_NODES * 32) return;
        int row = i >> 5, c4 = i & 31;
        float4 v = *(const float4*)(x + (size_t)row * D + c4 * 4);
        __nv_bfloat16 h0 = __float2bfloat16(v.x), h1 = __float2bfloat16(v.y);
        __nv_bfloat16 h2 = __float2bfloat16(v.z), h3 = __float2bfloat16(v.w);
        uint2 hp, lp, fp;
        hp.x = pack2bf(v.x, v.y); hp.y = pack2bf(v.z, v.w);
        lp.x = pack2bf(v.x - __bfloat162float(h0), v.y - __bfloat162float(h1));
        lp.y = pack2bf(v.z - __bfloat162float(h2), v.w - __bfloat162float(h3));
        fp.x = pack2hf(v.x, v.y); fp.y = pack2hf(v.z, v.w);
        size_t off = (size_t)row * K2 + D + c4 * 4;
        *(uint2*)(g_Ahi + off) = hp;
        *(uint2*)(g_Alo + off) = lp;
        *(uint2*)(g_hf16 + (size_t)row * D + c4 * 4) = fp;
    } else if (b < K1_XB + K1_WB) {
        int i = (b - K1_XB) * 256 + threadIdx.x;   // < 98304
        int l = i / (128 * K2);
        int n = (i / K2) % 128;
        int k = i % K2;
        const float* Wl = (l == 0) ? Wl1 : (l == 1) ? Wl2 : Wl3;
        const float* Wr = (l == 0) ? Wr1 : (l == 1) ? Wr2 : Wr3;
        float v = (k < D) ? Wl[n * D + k] : Wr[n * D + (k - D)];
        __nv_bfloat16 hi = __float2bfloat16(v);
        g_Bhi[i] = hi;
        g_Blo[i] = __float2bfloat16(v - __bfloat162float(hi));
    } else {
        int i = (b - K1_XB - K1_WB) * 256 + threadIdx.x;
        if (i < N_NODES) g_cnt[i] = 0;
        if (i == 0) {
            int is64 = 1;
            for (int q = 0; q < 64; q++)
                if (ei32[2 * q + 1] != 0) { is64 = 0; break; }
            g_is64 = is64;
        }
    }
}

// ================ CSR build (all PDL-chained: sync, trigger, work) ===========
__global__ void count_kernel(const void* __restrict__ ei) {
    cudaGridDependencySynchronize();
    cudaTriggerProgrammaticLaunchCompletion();
    int e = blockIdx.x * blockDim.x + threadIdx.x;
    if (e < N_EDGES) atomicAdd(&g_cnt[edge_val(ei, N_EDGES + e)], 1);
}
__global__ void scan_partial_kernel() {
    cudaGridDependencySynchronize();
    cudaTriggerProgrammaticLaunchCompletion();
    __shared__ int s[1024];
    int i = blockIdx.x * 1024 + threadIdx.x;
    int v = (i < N_NODES) ? g_cnt[i] : 0;
    s[threadIdx.x] = v;
    __syncthreads();
    for (int off = 512; off > 0; off >>= 1) {
        if (threadIdx.x < off) s[threadIdx.x] += s[threadIdx.x + off];
        __syncthreads();
    }
    if (threadIdx.x == 0) g_bsum[blockIdx.x] = s[0];
}
__global__ void scan_write_kernel() {
    cudaGridDependencySynchronize();
    cudaTriggerProgrammaticLaunchCompletion();
    __shared__ int s[1024];
    __shared__ int pre[64];
    int i = blockIdx.x * 1024 + threadIdx.x;
    int v = (i < N_NODES) ? g_cnt[i] : 0;
    s[threadIdx.x] = v;
    if (threadIdx.x < 64)
        pre[threadIdx.x] = (threadIdx.x < blockIdx.x) ? g_bsum[threadIdx.x] : 0;
    __syncthreads();
    if (threadIdx.x < 32) {
        int t = pre[threadIdx.x] + pre[threadIdx.x + 32];
        for (int off = 16; off > 0; off >>= 1)
            t += __shfl_down_sync(0xFFFFFFFF, t, off);
        if (threadIdx.x == 0) pre[0] = t;
    }
    __syncthreads();
    int s_pre = pre[0];
    for (int off = 1; off < 1024; off <<= 1) {
        int t = (threadIdx.x >= off) ? s[threadIdx.x - off] : 0;
        __syncthreads();
        s[threadIdx.x] += t;
        __syncthreads();
    }
    if (i < N_NODES) {
        int excl = s[threadIdx.x] - v + s_pre;
        g_rowptr[i] = excl;
        g_cursor[i] = excl;
        if (i == N_NODES - 1) g_rowptr[N_NODES] = excl + v;
    }
}
__global__ void fill_kernel(const void* __restrict__ ei) {
    cudaGridDependencySynchronize();
    cudaTriggerProgrammaticLaunchCompletion();
    int e = blockIdx.x * blockDim.x + threadIdx.x;
    if (e < N_EDGES) {
        int d = edge_val(ei, N_EDGES + e);
        int s = edge_val(ei, e);
        g_srcidx[atomicAdd(&g_cursor[d], 1)] = s;
    }
}

// ===== mean aggregation (warp/node, fp16 gather) -> bf16 hi/lo A cols [0,128)
// sync (prior gemm/fill fully done) THEN trigger: this ordering guarantees the
// dependent gemm only launches after the previous gemm's epilogue is complete,
// so its self-column prefetch cannot race.
__global__ __launch_bounds__(256)
void agg_kernel() {
    cudaGridDependencySynchronize();
    cudaTriggerProgrammaticLaunchCompletion();
    int warp = (blockIdx.x * blockDim.x + threadIdx.x) >> 5;
    int lane = threadIdx.x & 31;
    if (warp >= N_NODES) return;
    int beg = g_rowptr[warp];
    int end = g_rowptr[warp + 1];
    float4 s0 = make_float4(0.f,0.f,0.f,0.f), s1 = s0, s2 = s0, s3 = s0;
    const __half* hp16 = g_hf16;
    int e = beg;
    for (; e + 4 <= end; e += 4) {
        int j0 = g_srcidx[e],     j1 = g_srcidx[e + 1];
        int j2 = g_srcidx[e + 2], j3 = g_srcidx[e + 3];
        uint2 r0 = *(const uint2*)(hp16 + (size_t)j0 * D + lane * 4);
        uint2 r1 = *(const uint2*)(hp16 + (size_t)j1 * D + lane * 4);
        uint2 r2 = *(const uint2*)(hp16 + (size_t)j2 * D + lane * 4);
        uint2 r3 = *(const uint2*)(hp16 + (size_t)j3 * D + lane * 4);
        float2 a0 = __half22float2(*(__half2*)&r0.x), b0 = __half22float2(*(__half2*)&r0.y);
        float2 a1 = __half22float2(*(__half2*)&r1.x), b1 = __half22float2(*(__half2*)&r1.y);
        float2 a2 = __half22float2(*(__half2*)&r2.x), b2 = __half22float2(*(__half2*)&r2.y);
        float2 a3 = __half22float2(*(__half2*)&r3.x), b3 = __half22float2(*(__half2*)&r3.y);
        s0.x += a0.x; s0.y += a0.y; s0.z += b0.x; s0.w += b0.y;
        s1.x += a1.x; s1.y += a1.y; s1.z += b1.x; s1.w += b1.y;
        s2.x += a2.x; s2.y += a2.y; s2.z += b2.x; s2.w += b2.y;
        s3.x += a3.x; s3.y += a3.y; s3.z += b3.x; s3.w += b3.y;
    }
    for (; e < end; e++) {
        int j = g_srcidx[e];
        uint2 r = *(const uint2*)(hp16 + (size_t)j * D + lane * 4);
        float2 a = __half22float2(*(__half2*)&r.x), b = __half22float2(*(__half2*)&r.y);
        s0.x += a.x; s0.y += a.y; s0.z += b.x; s0.w += b.y;
    }
    float inv = 1.0f / fmaxf((float)(end - beg), 1.0f);
    float4 m;
    m.x = ((s0.x + s1.x) + (s2.x + s3.x)) * inv;
    m.y = ((s0.y + s1.y) + (s2.y + s3.y)) * inv;
    m.z = ((s0.z + s1.z) + (s2.z + s3.z)) * inv;
    m.w = ((s0.w + s1.w) + (s2.w + s3.w)) * inv;
    __nv_bfloat16 h0 = __float2bfloat16(m.x), h1 = __float2bfloat16(m.y);
    __nv_bfloat16 h2 = __float2bfloat16(m.z), h3 = __float2bfloat16(m.w);
    uint2 hp, lp;
    hp.x = pack2bf(m.x, m.y); hp.y = pack2bf(m.z, m.w);
    lp.x = pack2bf(m.x - __bfloat162float(h0), m.y - __bfloat162float(h1));
    lp.y = pack2bf(m.z - __bfloat162float(h2), m.w - __bfloat162float(h3));
    size_t off = (size_t)warp * K2 + lane * 4;
    *(uint2*)(g_Ahi + off) = hp;
    *(uint2*)(g_Alo + off) = lp;
}

// ================= bf16 mma.sync GEMM (PDL secondary) ========================
// Chunks 0..5: self cols [128,256) (pre-gridDepSync); 6..11: agg cols [0,128).
#define TILE_B  16384
#define SM_BIAS 0
#define SM_A0   1024
#define SM_B0   (1024 + 2 * TILE_B)
#define SM_TOTAL (1024 + 4 * TILE_B)   // 66560 -> 3 CTAs/SM

__constant__ int c_aNew[12] = {1,0,1,0,1,1, 1,0,1,0,1,1};
__constant__ int c_aBuf[12] = {0,0,1,1,0,1, 0,0,1,1,0,1};
__constant__ int c_aHi[12]  = {1,1,1,1,0,0, 1,1,1,1,0,0};
__constant__ int c_bHi[12]  = {1,0,1,0,1,1, 1,0,1,0,1,1};
__constant__ int c_K[12]    = {128,128,192,192,128,192, 0,0,64,64,0,64};

__global__ __launch_bounds__(256)
void gemm_tc(const __nv_bfloat16* __restrict__ Bhi, const __nv_bfloat16* __restrict__ Blo,
             const float* __restrict__ bias, float* __restrict__ out,
             int write_next) {
    extern __shared__ char smem[];
    const uint32_t sb = smem_u32(smem);
    const int tid = threadIdx.x;
    const int wid = tid >> 5, lane = tid & 31;
    const int wm = wid >> 2, wn = wid & 3;
    const int m0 = blockIdx.x * 128;

    if (tid < 128) *(float*)(smem + SM_BIAS + tid * 4) = bias[tid];

    float acc[4][4][4];
#pragma unroll
    for (int i = 0; i < 4; i++)
#pragma unroll
        for (int j = 0; j < 4; j++)
#pragma unroll
            for (int q = 0; q < 4; q++) acc[i][j][q] = 0.f;

    auto prefetch = [&](int s) {
        int k0 = c_K[s];
        const __nv_bfloat16* Bp = c_bHi[s] ? Bhi : Blo;
        uint32_t sB = sb + SM_B0 + (s & 1) * TILE_B;
#pragma unroll
        for (int t = 0; t < 4; t++) {
            int u = tid + t * 256;
            int row = u >> 3, f4 = u & 7;
            cp_async16(sB + SWZ128((uint32_t)(row * 128 + f4 * 16)),
                       Bp + (size_t)row * K2 + k0 + f4 * 8);
        }
        if (c_aNew[s]) {
            const __nv_bfloat16* Ap = c_aHi[s] ? g_Ahi : g_Alo;
            uint32_t sA = sb + SM_A0 + c_aBuf[s] * TILE_B;
#pragma unroll
            for (int t = 0; t < 4; t++) {
                int u = tid + t * 256;
                int row = u >> 3, f4 = u & 7;
                int gm = m0 + row;
                if (gm >= N_NODES) gm = N_NODES - 1;
                cp_async16(sA + SWZ128((uint32_t)(row * 128 + f4 * 16)),
                           Ap + (size_t)gm * K2 + k0 + f4 * 8);
            }
        }
    };

    prefetch(0);
    CP_COMMIT();

    for (int s = 0; s < 12; s++) {
        CP_WAIT0();
        __syncthreads();
        if (s + 1 == 6) cudaGridDependencySynchronize();   // agg cols ready
        if (s + 1 < 12) { prefetch(s + 1); CP_COMMIT(); }

        uint32_t sA = sb + SM_A0 + c_aBuf[s] * TILE_B;
        uint32_t sB = sb + SM_B0 + (s & 1) * TILE_B;
#pragma unroll
        for (int kk = 0; kk < 4; kk++) {
            uint32_t a[4][4], b[4][2];
#pragma unroll
            for (int mf = 0; mf < 4; mf++) {
                int row  = wm * 64 + mf * 16 + (lane & 15);
                int colb = kk * 32 + (lane >> 4) * 16;
                ldsm_x4(a[mf], sA + SWZ128((uint32_t)(row * 128 + colb)));
            }
#pragma unroll
            for (int nh = 0; nh < 2; nh++) {
                uint32_t r[4];
                int row  = wn * 32 + nh * 16 + (lane & 7) + ((lane >> 4) << 3);
                int colb = kk * 32 + ((lane >> 3) & 1) * 16;
                ldsm_x4(r, sB + SWZ128((uint32_t)(row * 128 + colb)));
                b[nh * 2][0] = r[0]; b[nh * 2][1] = r[1];
                b[nh * 2 + 1][0] = r[2]; b[nh * 2 + 1][1] = r[3];
            }
#pragma unroll
            for (int mf = 0; mf < 4; mf++)
#pragma unroll
                for (int nf = 0; nf < 4; nf++)
                    mma_bf16(acc[mf][nf], a[mf], b[nf]);
        }
        __syncthreads();
    }

    // MMA done -> let next layer's agg become resident while epilogue runs
    cudaTriggerProgrammaticLaunchCompletion();

    // epilogue: bias + relu.
    const int qr = lane >> 2;
    const int qc = (lane & 3) * 2;
#pragma unroll
    for (int mf = 0; mf < 4; mf++) {
        int r0 = m0 + wm * 64 + mf * 16 + qr;
        int r1 = r0 + 8;
#pragma unroll
        for (int nf = 0; nf < 4; nf++) {
            int col = wn * 32 + nf * 8 + qc;
            float b0 = *(const float*)(smem + SM_BIAS + col * 4);
            float b1 = *(const float*)(smem + SM_BIAS + (col + 1) * 4);
            float v00 = fmaxf(acc[mf][nf][0] + b0, 0.f);
            float v01 = fmaxf(acc[mf][nf][1] + b1, 0.f);
            float v10 = fmaxf(acc[mf][nf][2] + b0, 0.f);
            float v11 = fmaxf(acc[mf][nf][3] + b1, 0.f);
            if (r0 < N_NODES) {
                if (write_next) {
                    __nv_bfloat16 h0 = __float2bfloat16(v00), h1 = __float2bfloat16(v01);
                    size_t off = (size_t)r0 * K2 + D + col;
                    *(uint32_t*)(g_Ahi + off) = pack2bf(v00, v01);
                    *(uint32_t*)(g_Alo + off) = pack2bf(v00 - __bfloat162float(h0),
                                                        v01 - __bfloat162float(h1));
                    *(uint32_t*)(g_hf16 + (size_t)r0 * D + col) = pack2hf(v00, v01);
                } else {
                    *(float2*)(out + (size_t)r0 * D + col) = make_float2(v00, v01);
                }
            }
            if (r1 < N_NODES) {
                if (write_next) {
                    __nv_bfloat16 h0 = __float2bfloat16(v10), h1 = __float2bfloat16(v11);
                    size_t off = (size_t)r1 * K2 + D + col;
                    *(uint32_t*)(g_Ahi + off) = pack2bf(v10, v11);
                    *(uint32_t*)(g_Alo + off) = pack2bf(v10 - __bfloat162float(h0),
                                                        v11 - __bfloat162float(h1));
                    *(uint32_t*)(g_hf16 + (size_t)r1 * D + col) = pack2hf(v10, v11);
                } else {
                    *(float2*)(out + (size_t)r1 * D + col) = make_float2(v10, v11);
                }
            }
        }
    }
}

// ================= launch ====================================================
template <typename K, typename... Args>
static void launch_pdl(K kern, dim3 grid, dim3 block, size_t smem, Args... args) {
    cudaLaunchConfig_t cfg = {};
    cfg.gridDim = grid;
    cfg.blockDim = block;
    cfg.dynamicSmemBytes = smem;
    cfg.stream = 0;
    cudaLaunchAttribute at[1];
    at[0].id = cudaLaunchAttributeProgrammaticStreamSerialization;
    at[0].val.programmaticStreamSerializationAllowed = 1;
    cfg.attrs = at;
    cfg.numAttrs = 1;
    cudaLaunchKernelEx(&cfg, kern, args...);
}

extern "C" void kernel_launch(void* const* d_in, const int* in_sizes, int n_in,
                              void* d_out, int out_size) {
    const float* x  = (const float*)d_in[0];
    const void*  ei = d_in[1];
    const float* Wl1 = (const float*)d_in[2];
    const float* bl1 = (const float*)d_in[3];
    const float* Wr1 = (const float*)d_in[4];
    const float* Wl2 = (const float*)d_in[5];
    const float* bl2 = (const float*)d_in[6];
    const float* Wr2 = (const float*)d_in[7];
    const float* Wl3 = (const float*)d_in[8];
    const float* bl3 = (const float*)d_in[9];
    const float* Wr3 = (const float*)d_in[10];
    float* out = (float*)d_out;

    __nv_bfloat16 *Bhi, *Blo;
    cudaGetSymbolAddress((void**)&Bhi, g_Bhi);
    cudaGetSymbolAddress((void**)&Blo, g_Blo);

    cudaFuncSetAttribute(gemm_tc, cudaFuncAttributeMaxDynamicSharedMemorySize, SM_TOTAL);

    const int AGG_GRID = (N_NODES * 32 + 255) / 256;

    // prologue (all PDL-chained)
    launch_pdl(prep_all_kernel, dim3(K1_XB + K1_WB + K1_ZB), dim3(256), 0,
               x, (const int*)ei, Wl1, Wr1, Wl2, Wr2, Wl3, Wr3);
    launch_pdl(count_kernel, dim3((N_EDGES + 255) / 256), dim3(256), 0, ei);
    launch_pdl(scan_partial_kernel, dim3(NCHUNK), dim3(1024), 0);
    launch_pdl(scan_write_kernel, dim3(NCHUNK), dim3(1024), 0);
    launch_pdl(fill_kernel, dim3((N_EDGES + 255) / 256), dim3(256), 0, ei);

    // layer 1
    launch_pdl(agg_kernel, dim3(AGG_GRID), dim3(256), 0);
    launch_pdl(gemm_tc, dim3(GEMM_GRID), dim3(256), SM_TOTAL,
               (const __nv_bfloat16*)Bhi, (const __nv_bfloat16*)Blo,
               bl1, (float*)nullptr, 1);
    // layer 2
    launch_pdl(agg_kernel, dim3(AGG_GRID), dim3(256), 0);
    launch_pdl(gemm_tc, dim3(GEMM_GRID), dim3(256), SM_TOTAL,
               (const __nv_bfloat16*)(Bhi + 128 * K2), (const __nv_bfloat16*)(Blo + 128 * K2),
               bl2, (float*)nullptr, 1);
    // layer 3 -> final output
    launch_pdl(agg_kernel, dim3(AGG_GRID), dim3(256), 0);
    launch_pdl(gemm_tc, dim3(GEMM_GRID), dim3(256), SM_TOTAL,
               (const __nv_bfloat16*)(Bhi + 2 * 128 * K2), (const __nv_bfloat16*)(Blo + 2 * 128 * K2),
               bl3, out, 0);
}